// round 1
// baseline (speedup 1.0000x reference)
#include <cuda_runtime.h>
#include <math.h>

#define SEQ   2048
#define BATCH 2
#define DMODEL 1024
#define NH    16
#define DH    64
#define HALF  32
#define BHN   (BATCH*NH)        // 32
#define MTOK  (BATCH*SEQ)       // 4096

// -------- scratch (device globals; no allocation allowed) --------
__device__ float g_qkv[(size_t)MTOK * 3 * DMODEL];   // 4096 x 3072
__device__ float g_q[(size_t)BHN * SEQ * DH];        // (bh, s, d)
__device__ float g_k[(size_t)BHN * SEQ * DH];
__device__ float g_v[(size_t)BHN * SEQ * DH];
__device__ float g_p[(size_t)BHN * SEQ * SEQ];       // scores / probs, 537 MB
__device__ float g_ao[(size_t)MTOK * DMODEL];        // attn out, (b*S+s, h*dh+d)

// ================= SGEMM: C[M,N] = A[M,K] @ B[K,N], row-major, all dims %128/%16 ==
__global__ __launch_bounds__(256) void sgemm128(const float* __restrict__ A,
                                                const float* __restrict__ Bm,
                                                float* __restrict__ C,
                                                int M, int N, int K)
{
    const int BM = 128, BN = 128, BK = 16;
    __shared__ float As[BK][BM];
    __shared__ float Bs[BK][BN];

    int tid = threadIdx.x;
    int tr = tid >> 4;       // 0..15
    int tc = tid & 15;       // 0..15
    const float* Ab = A + (size_t)blockIdx.y * BM * K;
    const float* Bb = Bm + (size_t)blockIdx.x * BN;

    float acc[8][8];
#pragma unroll
    for (int i = 0; i < 8; i++)
#pragma unroll
        for (int j = 0; j < 8; j++) acc[i][j] = 0.f;

    for (int k0 = 0; k0 < K; k0 += BK) {
        // A tile 128x16 -> As transposed
#pragma unroll
        for (int l = 0; l < 2; l++) {
            int id = tid + l * 256;          // float4 id 0..511
            int r = id >> 2;
            int c = (id & 3) * 4;
            float4 v = *(const float4*)(Ab + (size_t)r * K + k0 + c);
            As[c + 0][r] = v.x; As[c + 1][r] = v.y;
            As[c + 2][r] = v.z; As[c + 3][r] = v.w;
        }
        // B tile 16x128
#pragma unroll
        for (int l = 0; l < 2; l++) {
            int id = tid + l * 256;
            int r = id >> 5;
            int c = (id & 31) * 4;
            *(float4*)&Bs[r][c] = *(const float4*)(Bb + (size_t)(k0 + r) * N + c);
        }
        __syncthreads();

#pragma unroll
        for (int kk = 0; kk < BK; kk++) {
            float ra[8], rb[8];
            *(float4*)&ra[0] = *(float4*)&As[kk][tr * 8];
            *(float4*)&ra[4] = *(float4*)&As[kk][tr * 8 + 4];
            *(float4*)&rb[0] = *(float4*)&Bs[kk][tc * 8];
            *(float4*)&rb[4] = *(float4*)&Bs[kk][tc * 8 + 4];
#pragma unroll
            for (int i = 0; i < 8; i++)
#pragma unroll
                for (int j = 0; j < 8; j++) acc[i][j] += ra[i] * rb[j];
        }
        __syncthreads();
    }

#pragma unroll
    for (int i = 0; i < 8; i++) {
        float* Crow = C + (size_t)(blockIdx.y * BM + tr * 8 + i) * N + blockIdx.x * BN + tc * 8;
        *(float4*)Crow       = make_float4(acc[i][0], acc[i][1], acc[i][2], acc[i][3]);
        *(float4*)(Crow + 4) = make_float4(acc[i][4], acc[i][5], acc[i][6], acc[i][7]);
    }
}

// ================= RoPE + transpose to (bh, s, d); v copy =======================
__global__ __launch_bounds__(256) void rope_transpose(const float* __restrict__ rc,
                                                      const float* __restrict__ rs)
{
    int idx = blockIdx.x * blockDim.x + threadIdx.x;     // 0 .. BHN*SEQ*HALF
    if (idx >= BHN * SEQ * HALF) return;
    int t  = idx & (HALF - 1);          // pair index 0..31
    int s  = (idx >> 5) & (SEQ - 1);
    int bh = idx >> 16;                 // / (SEQ*HALF)
    int b  = bh >> 4;
    int h  = bh & (NH - 1);

    size_t src = ((size_t)(b * SEQ + s)) * (3 * DMODEL) + h * DH + 2 * t;
    float c  = rc[s * DH + 2 * t];
    float sn = rs[s * DH + 2 * t];

    float2 q = *(const float2*)(g_qkv + src);
    float2 k = *(const float2*)(g_qkv + src + DMODEL);
    float2 v = *(const float2*)(g_qkv + src + 2 * DMODEL);

    size_t dst = ((size_t)bh * SEQ + s) * DH + 2 * t;
    *(float2*)(g_q + dst) = make_float2(q.x * c - q.y * sn, q.y * c + q.x * sn);
    *(float2*)(g_k + dst) = make_float2(k.x * c - k.y * sn, k.y * c + k.x * sn);
    *(float2*)(g_v + dst) = v;
}

// ================= scores: dual-half dot + triangle select ======================
__global__ __launch_bounds__(256) void scores_kernel()
{
    __shared__ float Qs[64][65];
    __shared__ float Ks[64][65];
    int bh = blockIdx.z;
    int i0 = blockIdx.y * 64;
    int j0 = blockIdx.x * 64;
    const float* Qb = g_q + ((size_t)bh * SEQ + i0) * DH;
    const float* Kb = g_k + ((size_t)bh * SEQ + j0) * DH;

    int tid = threadIdx.x;
#pragma unroll
    for (int l = 0; l < 4; l++) {
        int id = tid + l * 256;          // float4 id 0..1023
        int r = id >> 4;
        int c = (id & 15) * 4;
        float4 v = *(const float4*)(Qb + (size_t)r * DH + c);
        Qs[r][c] = v.x; Qs[r][c + 1] = v.y; Qs[r][c + 2] = v.z; Qs[r][c + 3] = v.w;
        v = *(const float4*)(Kb + (size_t)r * DH + c);
        Ks[r][c] = v.x; Ks[r][c + 1] = v.y; Ks[r][c + 2] = v.z; Ks[r][c + 3] = v.w;
    }
    __syncthreads();

    int ty = tid >> 4, tx = tid & 15;
    float up[4][4], dn[4][4];
#pragma unroll
    for (int r = 0; r < 4; r++)
#pragma unroll
        for (int c = 0; c < 4; c++) { up[r][c] = 0.f; dn[r][c] = 0.f; }

#pragma unroll 8
    for (int d = 0; d < HALF; d++) {
        float qr[4], kr[4];
#pragma unroll
        for (int r = 0; r < 4; r++) qr[r] = Qs[ty * 4 + r][d];
#pragma unroll
        for (int c = 0; c < 4; c++) kr[c] = Ks[tx * 4 + c][d];
#pragma unroll
        for (int r = 0; r < 4; r++)
#pragma unroll
            for (int c = 0; c < 4; c++) up[r][c] += qr[r] * kr[c];
    }
#pragma unroll 8
    for (int d = HALF; d < DH; d++) {
        float qr[4], kr[4];
#pragma unroll
        for (int r = 0; r < 4; r++) qr[r] = Qs[ty * 4 + r][d];
#pragma unroll
        for (int c = 0; c < 4; c++) kr[c] = Ks[tx * 4 + c][d];
#pragma unroll
        for (int r = 0; r < 4; r++)
#pragma unroll
            for (int c = 0; c < 4; c++) dn[r][c] += qr[r] * kr[c];
    }

    const float scale = 0.17677669529663687f;   // 32^-0.5
#pragma unroll
    for (int r = 0; r < 4; r++) {
        int i = i0 + ty * 4 + r;
        float o[4];
#pragma unroll
        for (int c = 0; c < 4; c++) {
            int j = j0 + tx * 4 + c;
            o[c] = scale * ((j <= i) ? dn[r][c] : up[r][c]);
        }
        *(float4*)(g_p + ((size_t)bh * SEQ + i) * SEQ + j0 + tx * 4) =
            make_float4(o[0], o[1], o[2], o[3]);
    }
}

// ================= row softmax over S=2048 ======================================
__global__ __launch_bounds__(256) void softmax_kernel()
{
    size_t row = blockIdx.x;                 // bh*SEQ + i
    float* p = g_p + row * SEQ;
    int tid = threadIdx.x;

    float v[8];
    float4 a = *(const float4*)(p + tid * 8);
    float4 b = *(const float4*)(p + tid * 8 + 4);
    v[0]=a.x; v[1]=a.y; v[2]=a.z; v[3]=a.w; v[4]=b.x; v[5]=b.y; v[6]=b.z; v[7]=b.w;

    float m = v[0];
#pragma unroll
    for (int i = 1; i < 8; i++) m = fmaxf(m, v[i]);

    __shared__ float red[8];
#pragma unroll
    for (int off = 16; off > 0; off >>= 1) m = fmaxf(m, __shfl_xor_sync(0xffffffffu, m, off));
    if ((tid & 31) == 0) red[tid >> 5] = m;
    __syncthreads();
    if (tid < 8) {
        float mm = red[tid];
#pragma unroll
        for (int off = 4; off > 0; off >>= 1) mm = fmaxf(mm, __shfl_xor_sync(0xffu, mm, off));
        red[tid] = mm;
    }
    __syncthreads();
    m = red[0];

    float s = 0.f;
#pragma unroll
    for (int i = 0; i < 8; i++) { v[i] = __expf(v[i] - m); s += v[i]; }

    __shared__ float red2[8];
#pragma unroll
    for (int off = 16; off > 0; off >>= 1) s += __shfl_xor_sync(0xffffffffu, s, off);
    if ((tid & 31) == 0) red2[tid >> 5] = s;
    __syncthreads();
    if (tid < 8) {
        float ss = red2[tid];
#pragma unroll
        for (int off = 4; off > 0; off >>= 1) ss += __shfl_xor_sync(0xffu, ss, off);
        red2[tid] = ss;
    }
    __syncthreads();
    float inv = 1.f / red2[0];

#pragma unroll
    for (int i = 0; i < 8; i++) v[i] *= inv;
    *(float4*)(p + tid * 8)     = make_float4(v[0], v[1], v[2], v[3]);
    *(float4*)(p + tid * 8 + 4) = make_float4(v[4], v[5], v[6], v[7]);
}

// ================= attn_out = P @ V, per (bh) ===================================
__global__ __launch_bounds__(256) void pv_kernel()
{
    __shared__ float Ps[64][65];
    __shared__ float Vs[64][65];
    int bh = blockIdx.y;
    int i0 = blockIdx.x * 64;
    int b = bh >> 4, h = bh & (NH - 1);
    int tid = threadIdx.x;
    int ty = tid >> 4, tx = tid & 15;

    float acc[4][4];
#pragma unroll
    for (int r = 0; r < 4; r++)
#pragma unroll
        for (int c = 0; c < 4; c++) acc[r][c] = 0.f;

    for (int kt = 0; kt < SEQ / 64; kt++) {
        int k0 = kt * 64;
#pragma unroll
        for (int l = 0; l < 4; l++) {
            int id = tid + l * 256;
            int r = id >> 4;
            int c = (id & 15) * 4;
            float4 vp = *(const float4*)(g_p + ((size_t)bh * SEQ + i0 + r) * SEQ + k0 + c);
            Ps[r][c] = vp.x; Ps[r][c + 1] = vp.y; Ps[r][c + 2] = vp.z; Ps[r][c + 3] = vp.w;
            float4 vv = *(const float4*)(g_v + ((size_t)bh * SEQ + k0 + r) * DH + c);
            Vs[r][c] = vv.x; Vs[r][c + 1] = vv.y; Vs[r][c + 2] = vv.z; Vs[r][c + 3] = vv.w;
        }
        __syncthreads();

#pragma unroll 16
        for (int kk = 0; kk < 64; kk++) {
            float pr[4], vr[4];
#pragma unroll
            for (int r = 0; r < 4; r++) pr[r] = Ps[ty * 4 + r][kk];
#pragma unroll
            for (int c = 0; c < 4; c++) vr[c] = Vs[kk][tx * 4 + c];
#pragma unroll
            for (int r = 0; r < 4; r++)
#pragma unroll
                for (int c = 0; c < 4; c++) acc[r][c] += pr[r] * vr[c];
        }
        __syncthreads();
    }

#pragma unroll
    for (int r = 0; r < 4; r++) {
        int i = i0 + ty * 4 + r;
        *(float4*)(g_ao + ((size_t)(b * SEQ + i)) * DMODEL + h * DH + tx * 4) =
            make_float4(acc[r][0], acc[r][1], acc[r][2], acc[r][3]);
    }
}

// =================================================================================
extern "C" void kernel_launch(void* const* d_in, const int* in_sizes, int n_in,
                              void* d_out, int out_size)
{
    const float* x      = (const float*)d_in[0];
    const float* w_qkv  = (const float*)d_in[1];
    const float* w_proj = (const float*)d_in[2];
    const float* rc     = (const float*)d_in[3];
    const float* rs     = (const float*)d_in[4];
    float* out = (float*)d_out;

    float *qkv_ptr, *ao_ptr;
    cudaGetSymbolAddress((void**)&qkv_ptr, g_qkv);
    cudaGetSymbolAddress((void**)&ao_ptr,  g_ao);

    // 1) QKV GEMM: [4096,1024] @ [1024,3072]
    sgemm128<<<dim3(3 * DMODEL / 128, MTOK / 128), 256>>>(x, w_qkv, qkv_ptr,
                                                          MTOK, 3 * DMODEL, DMODEL);
    // 2) RoPE + transpose
    {
        int total = BHN * SEQ * HALF;
        rope_transpose<<<(total + 255) / 256, 256>>>(rc, rs);
    }
    // 3) scores with triangle select
    scores_kernel<<<dim3(SEQ / 64, SEQ / 64, BHN), 256>>>();
    // 4) softmax
    softmax_kernel<<<BHN * SEQ, 256>>>();
    // 5) P @ V
    pv_kernel<<<dim3(SEQ / 64, BHN), 256>>>();
    // 6) proj GEMM: [4096,1024] @ [1024,1024] -> out
    sgemm128<<<dim3(DMODEL / 128, MTOK / 128), 256>>>(ao_ptr, w_proj, out,
                                                      MTOK, DMODEL, DMODEL);
}

// round 2
// speedup vs baseline: 1.0298x; 1.0298x over previous
#include <cuda_runtime.h>
#include <math.h>

#define SEQ   2048
#define BATCH 2
#define DMODEL 1024
#define NH    16
#define DH    64
#define HALF  32
#define BHN   (BATCH*NH)        // 32
#define MTOK  (BATCH*SEQ)       // 4096

typedef unsigned long long u64;

// -------- scratch (device globals; no allocation allowed) --------
__device__ float g_qkv[(size_t)MTOK * 3 * DMODEL];   // 4096 x 3072
__device__ float g_q[(size_t)BHN * SEQ * DH];        // (bh, s, d)
__device__ float g_k[(size_t)BHN * SEQ * DH];
__device__ float g_v[(size_t)BHN * SEQ * DH];
__device__ float g_ao[(size_t)MTOK * DMODEL];        // attn out

// ---------------- f32x2 helpers ----------------
__device__ __forceinline__ u64 pack2(float lo, float hi) {
    u64 r; asm("mov.b64 %0,{%1,%2};" : "=l"(r) : "f"(lo), "f"(hi)); return r;
}
__device__ __forceinline__ float2 unpack2(u64 v) {
    float2 f; asm("mov.b64 {%0,%1},%2;" : "=f"(f.x), "=f"(f.y) : "l"(v)); return f;
}
__device__ __forceinline__ u64 ffma2(u64 a, u64 b, u64 c) {
    u64 d; asm("fma.rn.f32x2 %0,%1,%2,%3;" : "=l"(d) : "l"(a), "l"(b), "l"(c)); return d;
}
__device__ __forceinline__ u64 fmul2(u64 a, u64 b) {
    u64 d; asm("mul.rn.f32x2 %0,%1,%2;" : "=l"(d) : "l"(a), "l"(b)); return d;
}

// ================= SGEMM (f32x2): C[M,N] = A[M,K] @ B[K,N] ======================
// A stored dup-packed in smem so the packed inner loop needs no dup MOVs.
__global__ __launch_bounds__(256) void sgemm128(const float* __restrict__ A,
                                                const float* __restrict__ Bm,
                                                float* __restrict__ C,
                                                int M, int N, int K)
{
    const int BM = 128, BN = 128, BK = 16;
    __shared__ u64   As2[BK][BM];      // dup-packed A: 16KB
    __shared__ float Bs[BK][BN];       // 8KB

    int tid = threadIdx.x;
    int tr = tid >> 4;       // 0..15
    int tc = tid & 15;       // 0..15
    const float* Ab = A + (size_t)blockIdx.y * BM * K;
    const float* Bb = Bm + (size_t)blockIdx.x * BN;

    u64 acc2[8][4];
#pragma unroll
    for (int i = 0; i < 8; i++)
#pragma unroll
        for (int j = 0; j < 4; j++) acc2[i][j] = 0ull;

    for (int k0 = 0; k0 < K; k0 += BK) {
        // A tile 128x16 -> As2 transposed + dup-packed
#pragma unroll
        for (int l = 0; l < 2; l++) {
            int id = tid + l * 256;          // float4 id 0..511
            int r = id >> 2;
            int c = (id & 3) * 4;
            float4 v = *(const float4*)(Ab + (size_t)r * K + k0 + c);
            As2[c + 0][r] = pack2(v.x, v.x);
            As2[c + 1][r] = pack2(v.y, v.y);
            As2[c + 2][r] = pack2(v.z, v.z);
            As2[c + 3][r] = pack2(v.w, v.w);
        }
        // B tile 16x128
#pragma unroll
        for (int l = 0; l < 2; l++) {
            int id = tid + l * 256;
            int r = id >> 5;
            int c = (id & 31) * 4;
            *(float4*)&Bs[r][c] = *(const float4*)(Bb + (size_t)(k0 + r) * N + c);
        }
        __syncthreads();

#pragma unroll
        for (int kk = 0; kk < BK; kk++) {
            u64 ra2[8], rb2[4];
            ulonglong2 t;
            t = *(const ulonglong2*)&As2[kk][tr * 8 + 0]; ra2[0] = t.x; ra2[1] = t.y;
            t = *(const ulonglong2*)&As2[kk][tr * 8 + 2]; ra2[2] = t.x; ra2[3] = t.y;
            t = *(const ulonglong2*)&As2[kk][tr * 8 + 4]; ra2[4] = t.x; ra2[5] = t.y;
            t = *(const ulonglong2*)&As2[kk][tr * 8 + 6]; ra2[6] = t.x; ra2[7] = t.y;
            t = *(const ulonglong2*)&Bs[kk][tc * 8 + 0];  rb2[0] = t.x; rb2[1] = t.y;
            t = *(const ulonglong2*)&Bs[kk][tc * 8 + 4];  rb2[2] = t.x; rb2[3] = t.y;
#pragma unroll
            for (int i = 0; i < 8; i++)
#pragma unroll
                for (int j = 0; j < 4; j++) acc2[i][j] = ffma2(ra2[i], rb2[j], acc2[i][j]);
        }
        __syncthreads();
    }

#pragma unroll
    for (int i = 0; i < 8; i++) {
        float* Crow = C + (size_t)(blockIdx.y * BM + tr * 8 + i) * N + blockIdx.x * BN + tc * 8;
        float2 a0 = unpack2(acc2[i][0]), a1 = unpack2(acc2[i][1]);
        float2 a2 = unpack2(acc2[i][2]), a3 = unpack2(acc2[i][3]);
        *(float4*)Crow       = make_float4(a0.x, a0.y, a1.x, a1.y);
        *(float4*)(Crow + 4) = make_float4(a2.x, a2.y, a3.x, a3.y);
    }
}

// ================= RoPE + transpose to (bh, s, d); v copy =======================
__global__ __launch_bounds__(256) void rope_transpose(const float* __restrict__ rc,
                                                      const float* __restrict__ rs)
{
    int idx = blockIdx.x * blockDim.x + threadIdx.x;     // 0 .. BHN*SEQ*HALF
    if (idx >= BHN * SEQ * HALF) return;
    int t  = idx & (HALF - 1);          // pair index 0..31
    int s  = (idx >> 5) & (SEQ - 1);
    int bh = idx >> 16;                 // / (SEQ*HALF)
    int b  = bh >> 4;
    int h  = bh & (NH - 1);

    size_t src = ((size_t)(b * SEQ + s)) * (3 * DMODEL) + h * DH + 2 * t;
    float c  = rc[s * DH + 2 * t];
    float sn = rs[s * DH + 2 * t];

    float2 q = *(const float2*)(g_qkv + src);
    float2 k = *(const float2*)(g_qkv + src + DMODEL);
    float2 v = *(const float2*)(g_qkv + src + 2 * DMODEL);

    size_t dst = ((size_t)bh * SEQ + s) * DH + 2 * t;
    *(float2*)(g_q + dst) = make_float2(q.x * c - q.y * sn, q.y * c + q.x * sn);
    *(float2*)(g_k + dst) = make_float2(k.x * c - k.y * sn, k.y * c + k.x * sn);
    *(float2*)(g_v + dst) = v;
}

// ================= fused flash attention (dual-triangle select) =================
// Per block: one (bh, 64-row i-tile). Online softmax over 32 j-tiles of 64.
// Thread (ty,tx): S rows i=ty+16r, cols j=tx+16c; O rows same, cols e=tx+16c.
// All inner products packed along the reduction axis via fma.rn.f32x2.
union KPu {
    u64   k[32][64];    // K tile, (dpair, j), col-XOR-swizzled by dp
    float p[64][64];    // P tile, (i, j) natural
};

__global__ __launch_bounds__(256, 1) void flash_kernel()
{
    __shared__ u64  Qp[64][32];   // (i, dpair) natural row pairs, 16KB
    __shared__ KPu  KP;           // 16KB (K then reused for P)
    __shared__ float Vt[64 * 64]; // (e, j) XOR-swizzled, 16KB

    int tid = threadIdx.x;
    int tx = tid & 15, ty = tid >> 4;
    int bh = blockIdx.y;
    int i0 = blockIdx.x * 64;
    int b = bh >> 4, h = bh & (NH - 1);

    const float* Qg = g_q + ((size_t)bh * SEQ + i0) * DH;
    const float* Kg = g_k + (size_t)bh * SEQ * DH;
    const float* Vg = g_v + (size_t)bh * SEQ * DH;

    // ---- load Q tile once (pairs along d) ----
#pragma unroll
    for (int l = 0; l < 4; l++) {
        int id = tid + l * 256;
        int i = id >> 4;
        int f4 = id & 15;
        float4 v = *(const float4*)(Qg + (size_t)i * DH + f4 * 4);
        ulonglong2 w; w.x = pack2(v.x, v.y); w.y = pack2(v.z, v.w);
        *(ulonglong2*)&Qp[i][f4 * 2] = w;
    }

    u64 o2[4][4];
#pragma unroll
    for (int r = 0; r < 4; r++)
#pragma unroll
        for (int c = 0; c < 4; c++) o2[r][c] = 0ull;
    float m[4], l[4];
#pragma unroll
    for (int r = 0; r < 4; r++) { m[r] = -1e30f; l[r] = 0.f; }

    const float scale = 0.17677669529663687f;   // 32^-0.5

    for (int jt = 0; jt < SEQ / 64; jt++) {
        int j0 = jt * 64;
        __syncthreads();   // protect KP(P) and Vt from prev iteration readers

        // ---- load K tile transposed+paired (dp, j^dp) and V tile swizzled ----
#pragma unroll
        for (int lld = 0; lld < 4; lld++) {
            int id = tid + lld * 256;
            int j = id >> 4;
            int f4 = id & 15;
            float4 kv = *(const float4*)(Kg + (size_t)(j0 + j) * DH + f4 * 4);
            int dp0 = f4 * 2;
            KP.k[dp0][j ^ dp0]           = pack2(kv.x, kv.y);
            KP.k[dp0 + 1][j ^ (dp0 + 1)] = pack2(kv.z, kv.w);
            float4 vv = *(const float4*)(Vg + (size_t)(j0 + j) * DH + f4 * 4);
            int jp = j >> 1, jl = j & 1;
#pragma unroll
            for (int q = 0; q < 4; q++) {
                int e = f4 * 4 + q;
                float val = (q == 0) ? vv.x : (q == 1) ? vv.y : (q == 2) ? vv.z : vv.w;
                Vt[e * 64 + ((jp ^ (e & 15)) * 2 + jl)] = val;
            }
        }
        __syncthreads();

        // ---- S = dual-half QK^T, packed along d ----
        u64 up2[4][4], dn2[4][4];
#pragma unroll
        for (int r = 0; r < 4; r++)
#pragma unroll
            for (int c = 0; c < 4; c++) { up2[r][c] = 0ull; dn2[r][c] = 0ull; }

#pragma unroll
        for (int dp = 0; dp < 16; dp++) {
            u64 q2[4], k2[4];
#pragma unroll
            for (int r = 0; r < 4; r++) q2[r] = Qp[ty + 16 * r][dp];
#pragma unroll
            for (int c = 0; c < 4; c++) k2[c] = KP.k[dp][(tx + 16 * c) ^ dp];
#pragma unroll
            for (int r = 0; r < 4; r++)
#pragma unroll
                for (int c = 0; c < 4; c++) up2[r][c] = ffma2(q2[r], k2[c], up2[r][c]);
        }
#pragma unroll
        for (int dp = 16; dp < 32; dp++) {
            u64 q2[4], k2[4];
#pragma unroll
            for (int r = 0; r < 4; r++) q2[r] = Qp[ty + 16 * r][dp];
#pragma unroll
            for (int c = 0; c < 4; c++) k2[c] = KP.k[dp][(tx + 16 * c) ^ dp];
#pragma unroll
            for (int r = 0; r < 4; r++)
#pragma unroll
                for (int c = 0; c < 4; c++) dn2[r][c] = ffma2(q2[r], k2[c], dn2[r][c]);
        }

        // ---- select + scale + online softmax (registers) ----
        float s[4][4];
#pragma unroll
        for (int r = 0; r < 4; r++) {
            int i = i0 + ty + 16 * r;
#pragma unroll
            for (int c = 0; c < 4; c++) {
                int j = j0 + tx + 16 * c;
                float2 u = unpack2(up2[r][c]);
                float2 d = unpack2(dn2[r][c]);
                s[r][c] = scale * ((j <= i) ? (d.x + d.y) : (u.x + u.y));
            }
        }
#pragma unroll
        for (int r = 0; r < 4; r++) {
            float cm = fmaxf(fmaxf(s[r][0], s[r][1]), fmaxf(s[r][2], s[r][3]));
#pragma unroll
            for (int off = 8; off > 0; off >>= 1)
                cm = fmaxf(cm, __shfl_xor_sync(0xffffffffu, cm, off, 16));
            float nm = fmaxf(m[r], cm);
            float al = __expf(m[r] - nm);
            m[r] = nm;
            float rsum = 0.f;
#pragma unroll
            for (int c = 0; c < 4; c++) { s[r][c] = __expf(s[r][c] - nm); rsum += s[r][c]; }
#pragma unroll
            for (int off = 8; off > 0; off >>= 1)
                rsum += __shfl_xor_sync(0xffffffffu, rsum, off, 16);
            l[r] = l[r] * al + rsum;
            u64 al2 = pack2(al, al);
#pragma unroll
            for (int c = 0; c < 4; c++) o2[r][c] = fmul2(o2[r][c], al2);
        }

        __syncthreads();   // all K-reads done before P overwrites KP
#pragma unroll
        for (int r = 0; r < 4; r++)
#pragma unroll
            for (int c = 0; c < 4; c++)
                KP.p[ty + 16 * r][tx + 16 * c] = s[r][c];
        __syncthreads();

        // ---- O += P @ V, packed along j ----
#pragma unroll 8
        for (int jp = 0; jp < 32; jp++) {
            u64 p2[4], v2[4];
#pragma unroll
            for (int r = 0; r < 4; r++)
                p2[r] = *(const u64*)&KP.p[ty + 16 * r][2 * jp];
#pragma unroll
            for (int c = 0; c < 4; c++) {
                int e = tx + 16 * c;
                v2[c] = *(const u64*)&Vt[e * 64 + ((jp ^ (e & 15)) * 2)];
            }
#pragma unroll
            for (int r = 0; r < 4; r++)
#pragma unroll
                for (int c = 0; c < 4; c++) o2[r][c] = ffma2(p2[r], v2[c], o2[r][c]);
        }
    }

    // ---- epilogue ----
#pragma unroll
    for (int r = 0; r < 4; r++) {
        float invl = 1.f / l[r];
        int i = i0 + ty + 16 * r;
#pragma unroll
        for (int c = 0; c < 4; c++) {
            float2 t = unpack2(o2[r][c]);
            g_ao[(size_t)(b * SEQ + i) * DMODEL + h * DH + tx + 16 * c] = (t.x + t.y) * invl;
        }
    }
}

// =================================================================================
extern "C" void kernel_launch(void* const* d_in, const int* in_sizes, int n_in,
                              void* d_out, int out_size)
{
    const float* x      = (const float*)d_in[0];
    const float* w_qkv  = (const float*)d_in[1];
    const float* w_proj = (const float*)d_in[2];
    const float* rc     = (const float*)d_in[3];
    const float* rs     = (const float*)d_in[4];
    float* out = (float*)d_out;

    float *qkv_ptr, *ao_ptr;
    cudaGetSymbolAddress((void**)&qkv_ptr, g_qkv);
    cudaGetSymbolAddress((void**)&ao_ptr,  g_ao);

    // 1) QKV GEMM: [4096,1024] @ [1024,3072]
    sgemm128<<<dim3(3 * DMODEL / 128, MTOK / 128), 256>>>(x, w_qkv, qkv_ptr,
                                                          MTOK, 3 * DMODEL, DMODEL);
    // 2) RoPE + transpose
    {
        int total = BHN * SEQ * HALF;
        rope_transpose<<<(total + 255) / 256, 256>>>(rc, rs);
    }
    // 3) fused attention (scores + triangle select + softmax + PV)
    flash_kernel<<<dim3(SEQ / 64, BHN), 256>>>();
    // 4) proj GEMM: [4096,1024] @ [1024,1024] -> out
    sgemm128<<<dim3(DMODEL / 128, MTOK / 128), 256>>>(ao_ptr, w_proj, out,
                                                      MTOK, DMODEL, DMODEL);
}

// round 3
// speedup vs baseline: 1.2519x; 1.2156x over previous
#include <cuda_runtime.h>
#include <math.h>

#define SEQ   2048
#define BATCH 2
#define DMODEL 1024
#define NH    16
#define DH    64
#define HALF  32
#define BHN   (BATCH*NH)        // 32
#define MTOK  (BATCH*SEQ)       // 4096

typedef unsigned long long u64;

// -------- scratch (device globals; no allocation allowed) --------
__device__ float g_qkv[(size_t)MTOK * 3 * DMODEL];   // 4096 x 3072
__device__ float g_q[(size_t)BHN * SEQ * DH];        // (bh, s, d)
__device__ float g_k[(size_t)BHN * SEQ * DH];
__device__ float g_v[(size_t)BHN * SEQ * DH];
__device__ float g_ao[(size_t)MTOK * DMODEL];        // attn out

// ---------------- f32x2 helpers ----------------
__device__ __forceinline__ u64 pack2(float lo, float hi) {
    u64 r; asm("mov.b64 %0,{%1,%2};" : "=l"(r) : "f"(lo), "f"(hi)); return r;
}
__device__ __forceinline__ float2 unpack2(u64 v) {
    float2 f; asm("mov.b64 {%0,%1},%2;" : "=f"(f.x), "=f"(f.y) : "l"(v)); return f;
}
__device__ __forceinline__ u64 ffma2(u64 a, u64 b, u64 c) {
    u64 d; asm("fma.rn.f32x2 %0,%1,%2,%3;" : "=l"(d) : "l"(a), "l"(b), "l"(c)); return d;
}
__device__ __forceinline__ u64 fmul2(u64 a, u64 b) {
    u64 d; asm("mul.rn.f32x2 %0,%1,%2;" : "=l"(d) : "l"(a), "l"(b)); return d;
}

// ================= SGEMM (f32x2): C[M,N] = A[M,K] @ B[K,N] ======================
// Register tile split into two 4-row / 4-col chunks (base tr*4 and 64+tr*4) so
// every LDS.128 phase hits distinct banks. A dup-packed (broadcast reads), B
// natural pairs along N.
__global__ __launch_bounds__(256, 2) void sgemm128(const float* __restrict__ A,
                                                   const float* __restrict__ Bm,
                                                   float* __restrict__ C,
                                                   int M, int N, int K)
{
    const int BM = 128, BN = 128, BK = 16;
    __shared__ u64   As2[BK][BM];      // dup-packed A: 16KB
    __shared__ float Bs[BK][BN];       // 8KB

    int tid = threadIdx.x;
    int tr = tid >> 4;       // 0..15
    int tc = tid & 15;       // 0..15
    const float* Ab = A + (size_t)blockIdx.y * BM * K;
    const float* Bb = Bm + (size_t)blockIdx.x * BN;

    u64 acc2[8][4];
#pragma unroll
    for (int i = 0; i < 8; i++)
#pragma unroll
        for (int j = 0; j < 4; j++) acc2[i][j] = 0ull;

    for (int k0 = 0; k0 < K; k0 += BK) {
        // A tile 128x16 -> As2 transposed + dup-packed
#pragma unroll
        for (int l = 0; l < 2; l++) {
            int id = tid + l * 256;          // float4 id 0..511
            int r = id >> 2;
            int c = (id & 3) * 4;
            float4 v = *(const float4*)(Ab + (size_t)r * K + k0 + c);
            As2[c + 0][r] = pack2(v.x, v.x);
            As2[c + 1][r] = pack2(v.y, v.y);
            As2[c + 2][r] = pack2(v.z, v.z);
            As2[c + 3][r] = pack2(v.w, v.w);
        }
        // B tile 16x128
#pragma unroll
        for (int l = 0; l < 2; l++) {
            int id = tid + l * 256;
            int r = id >> 5;
            int c = (id & 31) * 4;
            *(float4*)&Bs[r][c] = *(const float4*)(Bb + (size_t)(k0 + r) * N + c);
        }
        __syncthreads();

#pragma unroll
        for (int kk = 0; kk < BK; kk++) {
            u64 ra2[8], rb2[4];
            ulonglong2 t;
            t = *(const ulonglong2*)&As2[kk][tr * 4 + 0];      ra2[0] = t.x; ra2[1] = t.y;
            t = *(const ulonglong2*)&As2[kk][tr * 4 + 2];      ra2[2] = t.x; ra2[3] = t.y;
            t = *(const ulonglong2*)&As2[kk][64 + tr * 4 + 0]; ra2[4] = t.x; ra2[5] = t.y;
            t = *(const ulonglong2*)&As2[kk][64 + tr * 4 + 2]; ra2[6] = t.x; ra2[7] = t.y;
            t = *(const ulonglong2*)&Bs[kk][tc * 4];           rb2[0] = t.x; rb2[1] = t.y;
            t = *(const ulonglong2*)&Bs[kk][64 + tc * 4];      rb2[2] = t.x; rb2[3] = t.y;
#pragma unroll
            for (int i = 0; i < 8; i++)
#pragma unroll
                for (int j = 0; j < 4; j++) acc2[i][j] = ffma2(ra2[i], rb2[j], acc2[i][j]);
        }
        __syncthreads();
    }

#pragma unroll
    for (int i = 0; i < 8; i++) {
        int row = (i < 4) ? (tr * 4 + i) : (64 + tr * 4 + i - 4);
        float* Crow = C + (size_t)(blockIdx.y * BM + row) * N + blockIdx.x * BN;
        float2 a0 = unpack2(acc2[i][0]), a1 = unpack2(acc2[i][1]);
        float2 a2 = unpack2(acc2[i][2]), a3 = unpack2(acc2[i][3]);
        *(float4*)(Crow + tc * 4)      = make_float4(a0.x, a0.y, a1.x, a1.y);
        *(float4*)(Crow + 64 + tc * 4) = make_float4(a2.x, a2.y, a3.x, a3.y);
    }
}

// ================= RoPE + transpose to (bh, s, d); v copy =======================
__global__ __launch_bounds__(256) void rope_transpose(const float* __restrict__ rc,
                                                      const float* __restrict__ rs)
{
    int idx = blockIdx.x * blockDim.x + threadIdx.x;     // 0 .. BHN*SEQ*HALF
    if (idx >= BHN * SEQ * HALF) return;
    int t  = idx & (HALF - 1);          // pair index 0..31
    int s  = (idx >> 5) & (SEQ - 1);
    int bh = idx >> 16;                 // / (SEQ*HALF)
    int b  = bh >> 4;
    int h  = bh & (NH - 1);

    size_t src = ((size_t)(b * SEQ + s)) * (3 * DMODEL) + h * DH + 2 * t;
    float c  = rc[s * DH + 2 * t];
    float sn = rs[s * DH + 2 * t];

    float2 q = *(const float2*)(g_qkv + src);
    float2 k = *(const float2*)(g_qkv + src + DMODEL);
    float2 v = *(const float2*)(g_qkv + src + 2 * DMODEL);

    size_t dst = ((size_t)bh * SEQ + s) * DH + 2 * t;
    *(float2*)(g_q + dst) = make_float2(q.x * c - q.y * sn, q.y * c + q.x * sn);
    *(float2*)(g_k + dst) = make_float2(k.x * c - k.y * sn, k.y * c + k.x * sn);
    *(float2*)(g_v + dst) = v;
}

// ================= fused flash attention (dual-triangle select) =================
// Per block: one (bh, 64-row i-tile). 32 j-tiles; off-diagonal tiles compute only
// the needed half of d (16 dpairs), diagonal computes both + select.
// All smem XOR-swizzled by (row&15) so hot LDS paths are conflict-free.
union KPu {
    u64   k[64][32];    // K tile: row j, col dp^(j&15)
    float p[64 * 64];   // P tile: float at i*64 + (jp^(i&15))*2 + (j&1)
};

__global__ __launch_bounds__(256, 2) void flash_kernel()
{
    __shared__ u64  Qp[64][32];   // row i, col dp^(i&15)
    __shared__ KPu  KP;
    __shared__ u64  Vt[64][32];   // row e, col jp^(e&15), value (V[2jp][e], V[2jp+1][e])

    int tid = threadIdx.x;
    int tx = tid & 15, ty = tid >> 4;
    int it = blockIdx.x;
    int bh = blockIdx.y;
    int i0 = it * 64;
    int b = bh >> 4, h = bh & (NH - 1);

    const float* Qg = g_q + ((size_t)bh * SEQ + i0) * DH;
    const float* Kg = g_k + (size_t)bh * SEQ * DH;
    const float* Vg = g_v + (size_t)bh * SEQ * DH;

    // ---- load Q tile once (pairs along d, XOR-swizzled) ----
#pragma unroll
    for (int l = 0; l < 4; l++) {
        int id = tid + l * 256;
        int i = id >> 4;
        int f4 = id & 15;
        int sw = i & 15;
        float4 v = *(const float4*)(Qg + (size_t)i * DH + f4 * 4);
        Qp[i][(f4 * 2) ^ sw]     = pack2(v.x, v.y);
        Qp[i][(f4 * 2 + 1) ^ sw] = pack2(v.z, v.w);
    }

    u64 o2[4][4];
#pragma unroll
    for (int r = 0; r < 4; r++)
#pragma unroll
        for (int c = 0; c < 4; c++) o2[r][c] = 0ull;
    float m[4], l[4];
#pragma unroll
    for (int r = 0; r < 4; r++) { m[r] = -1e30f; l[r] = 0.f; }

    const float scale = 0.17677669529663687f;   // 32^-0.5

    for (int jt = 0; jt < SEQ / 64; jt++) {
        int j0 = jt * 64;
        __syncthreads();   // prior PV reads of KP.p / Vt done

        // ---- load K tile (row j, dpairs XOR-swizzled) ----
#pragma unroll
        for (int lld = 0; lld < 4; lld++) {
            int id = tid + lld * 256;
            int j = id >> 4;
            int f4 = id & 15;
            int sw = j & 15;
            float4 kv = *(const float4*)(Kg + (size_t)(j0 + j) * DH + f4 * 4);
            KP.k[j][(f4 * 2) ^ sw]     = pack2(kv.x, kv.y);
            KP.k[j][(f4 * 2 + 1) ^ sw] = pack2(kv.z, kv.w);
        }
        // ---- load V transposed into jpair u64s: Vt[e][jp^(e&15)] ----
#pragma unroll
        for (int lld = 0; lld < 4; lld++) {
            int id = tid + lld * 256;
            int jp = id >> 5;          // 0..31
            int e = (id & 31) * 2;     // 0..62 even
            float2 a = *(const float2*)(Vg + (size_t)(j0 + 2 * jp) * DH + e);
            float2 c = *(const float2*)(Vg + (size_t)(j0 + 2 * jp + 1) * DH + e);
            Vt[e][jp ^ (e & 15)]           = pack2(a.x, c.x);
            Vt[e + 1][jp ^ ((e + 1) & 15)] = pack2(a.y, c.y);
        }
        __syncthreads();

        // ---- S tile: only the needed half of d (both on the diagonal tile) ----
        float s[4][4];
        if (jt != it) {
            int dbase = (jt < it) ? 16 : 0;    // lower -> dn half, upper -> up half
            u64 s2[4][4];
#pragma unroll
            for (int r = 0; r < 4; r++)
#pragma unroll
                for (int c = 0; c < 4; c++) s2[r][c] = 0ull;
#pragma unroll
            for (int dd = 0; dd < 16; dd++) {
                int dp = dbase + dd;
                u64 q2[4], k2[4];
#pragma unroll
                for (int r = 0; r < 4; r++) q2[r] = Qp[ty + 16 * r][dp ^ ty];
#pragma unroll
                for (int c = 0; c < 4; c++) k2[c] = KP.k[tx + 16 * c][dp ^ tx];
#pragma unroll
                for (int r = 0; r < 4; r++)
#pragma unroll
                    for (int c = 0; c < 4; c++) s2[r][c] = ffma2(q2[r], k2[c], s2[r][c]);
            }
#pragma unroll
            for (int r = 0; r < 4; r++)
#pragma unroll
                for (int c = 0; c < 4; c++) {
                    float2 u = unpack2(s2[r][c]);
                    s[r][c] = scale * (u.x + u.y);
                }
        } else {
            u64 up2[4][4], dn2[4][4];
#pragma unroll
            for (int r = 0; r < 4; r++)
#pragma unroll
                for (int c = 0; c < 4; c++) { up2[r][c] = 0ull; dn2[r][c] = 0ull; }
#pragma unroll
            for (int dp = 0; dp < 16; dp++) {
                u64 q2[4], k2[4];
#pragma unroll
                for (int r = 0; r < 4; r++) q2[r] = Qp[ty + 16 * r][dp ^ ty];
#pragma unroll
                for (int c = 0; c < 4; c++) k2[c] = KP.k[tx + 16 * c][dp ^ tx];
#pragma unroll
                for (int r = 0; r < 4; r++)
#pragma unroll
                    for (int c = 0; c < 4; c++) up2[r][c] = ffma2(q2[r], k2[c], up2[r][c]);
            }
#pragma unroll
            for (int dp = 16; dp < 32; dp++) {
                u64 q2[4], k2[4];
#pragma unroll
                for (int r = 0; r < 4; r++) q2[r] = Qp[ty + 16 * r][dp ^ ty];
#pragma unroll
                for (int c = 0; c < 4; c++) k2[c] = KP.k[tx + 16 * c][dp ^ tx];
#pragma unroll
                for (int r = 0; r < 4; r++)
#pragma unroll
                    for (int c = 0; c < 4; c++) dn2[r][c] = ffma2(q2[r], k2[c], dn2[r][c]);
            }
#pragma unroll
            for (int r = 0; r < 4; r++) {
                int i = i0 + ty + 16 * r;
#pragma unroll
                for (int c = 0; c < 4; c++) {
                    int j = j0 + tx + 16 * c;
                    float2 u = unpack2(up2[r][c]);
                    float2 d = unpack2(dn2[r][c]);
                    s[r][c] = scale * ((j <= i) ? (d.x + d.y) : (u.x + u.y));
                }
            }
        }

        // ---- online softmax (registers + width-16 shuffles) ----
#pragma unroll
        for (int r = 0; r < 4; r++) {
            float cm = fmaxf(fmaxf(s[r][0], s[r][1]), fmaxf(s[r][2], s[r][3]));
#pragma unroll
            for (int off = 8; off > 0; off >>= 1)
                cm = fmaxf(cm, __shfl_xor_sync(0xffffffffu, cm, off, 16));
            float nm = fmaxf(m[r], cm);
            float al = __expf(m[r] - nm);
            m[r] = nm;
            float rsum = 0.f;
#pragma unroll
            for (int c = 0; c < 4; c++) { s[r][c] = __expf(s[r][c] - nm); rsum += s[r][c]; }
#pragma unroll
            for (int off = 8; off > 0; off >>= 1)
                rsum += __shfl_xor_sync(0xffffffffu, rsum, off, 16);
            l[r] = l[r] * al + rsum;
            u64 al2 = pack2(al, al);
#pragma unroll
            for (int c = 0; c < 4; c++) o2[r][c] = fmul2(o2[r][c], al2);
        }

        __syncthreads();   // K reads done before P overwrites KP
#pragma unroll
        for (int r = 0; r < 4; r++) {
            int i = ty + 16 * r;
#pragma unroll
            for (int c = 0; c < 4; c++) {
                int j = tx + 16 * c;
                KP.p[i * 64 + ((j >> 1) ^ ty) * 2 + (j & 1)] = s[r][c];
            }
        }
        __syncthreads();

        // ---- O += P @ V, packed along j pairs ----
#pragma unroll 8
        for (int jp = 0; jp < 32; jp++) {
            u64 p2[4], v2[4];
#pragma unroll
            for (int r = 0; r < 4; r++)
                p2[r] = *(const u64*)&KP.p[(ty + 16 * r) * 64 + ((jp ^ ty) * 2)];
#pragma unroll
            for (int c = 0; c < 4; c++)
                v2[c] = Vt[tx + 16 * c][jp ^ tx];
#pragma unroll
            for (int r = 0; r < 4; r++)
#pragma unroll
                for (int c = 0; c < 4; c++) o2[r][c] = ffma2(p2[r], v2[c], o2[r][c]);
        }
    }

    // ---- epilogue ----
#pragma unroll
    for (int r = 0; r < 4; r++) {
        float invl = 1.f / l[r];
        int i = i0 + ty + 16 * r;
#pragma unroll
        for (int c = 0; c < 4; c++) {
            float2 t = unpack2(o2[r][c]);
            g_ao[(size_t)(b * SEQ + i) * DMODEL + h * DH + tx + 16 * c] = (t.x + t.y) * invl;
        }
    }
}

// =================================================================================
extern "C" void kernel_launch(void* const* d_in, const int* in_sizes, int n_in,
                              void* d_out, int out_size)
{
    const float* x      = (const float*)d_in[0];
    const float* w_qkv  = (const float*)d_in[1];
    const float* w_proj = (const float*)d_in[2];
    const float* rc     = (const float*)d_in[3];
    const float* rs     = (const float*)d_in[4];
    float* out = (float*)d_out;

    float *qkv_ptr, *ao_ptr;
    cudaGetSymbolAddress((void**)&qkv_ptr, g_qkv);
    cudaGetSymbolAddress((void**)&ao_ptr,  g_ao);

    // 1) QKV GEMM: [4096,1024] @ [1024,3072]
    sgemm128<<<dim3(3 * DMODEL / 128, MTOK / 128), 256>>>(x, w_qkv, qkv_ptr,
                                                          MTOK, 3 * DMODEL, DMODEL);
    // 2) RoPE + transpose
    {
        int total = BHN * SEQ * HALF;
        rope_transpose<<<(total + 255) / 256, 256>>>(rc, rs);
    }
    // 3) fused attention (scores + triangle select + softmax + PV)
    flash_kernel<<<dim3(SEQ / 64, BHN), 256>>>();
    // 4) proj GEMM: [4096,1024] @ [1024,1024] -> out
    sgemm128<<<dim3(DMODEL / 128, MTOK / 128), 256>>>(ao_ptr, w_proj, out,
                                                      MTOK, DMODEL, DMODEL);
}

// round 5
// speedup vs baseline: 1.7440x; 1.3931x over previous
#include <cuda_runtime.h>
#include <cuda_bf16.h>
#include <math.h>
#include <cstdint>

#define SEQ   2048
#define BATCH 2
#define DMODEL 1024
#define NH    16
#define DH    64
#define HALF  32
#define BHN   (BATCH*NH)        // 32
#define MTOK  (BATCH*SEQ)       // 4096

typedef unsigned long long u64;
typedef __nv_bfloat16 bf16;

// -------- scratch (device globals; no allocation allowed) --------
__device__ float g_qkv[(size_t)MTOK * 3 * DMODEL];   // 4096 x 3072
__device__ float g_q[(size_t)BHN * SEQ * DH];
__device__ float g_k[(size_t)BHN * SEQ * DH];
__device__ float g_v[(size_t)BHN * SEQ * DH];
__device__ float g_ao[(size_t)MTOK * DMODEL];

__device__ bf16 g_xh[(size_t)MTOK * DMODEL];
__device__ bf16 g_xl[(size_t)MTOK * DMODEL];
__device__ bf16 g_aoh[(size_t)MTOK * DMODEL];
__device__ bf16 g_aol[(size_t)MTOK * DMODEL];
__device__ bf16 g_wqh[(size_t)3 * DMODEL * DMODEL];  // [3072][1024] transposed
__device__ bf16 g_wql[(size_t)3 * DMODEL * DMODEL];
__device__ bf16 g_wph[(size_t)DMODEL * DMODEL];      // [1024][1024] transposed
__device__ bf16 g_wpl[(size_t)DMODEL * DMODEL];

// ---------------- f32x2 helpers (flash kernel) ----------------
__device__ __forceinline__ u64 pack2(float lo, float hi) {
    u64 r; asm("mov.b64 %0,{%1,%2};" : "=l"(r) : "f"(lo), "f"(hi)); return r;
}
__device__ __forceinline__ float2 unpack2(u64 v) {
    float2 f; asm("mov.b64 {%0,%1},%2;" : "=f"(f.x), "=f"(f.y) : "l"(v)); return f;
}
__device__ __forceinline__ u64 ffma2(u64 a, u64 b, u64 c) {
    u64 d; asm("fma.rn.f32x2 %0,%1,%2,%3;" : "=l"(d) : "l"(a), "l"(b), "l"(c)); return d;
}
__device__ __forceinline__ u64 fmul2(u64 a, u64 b) {
    u64 d; asm("mul.rn.f32x2 %0,%1,%2;" : "=l"(d) : "l"(a), "l"(b)); return d;
}

// ---------------- mma.sync helpers ----------------
__device__ __forceinline__ uint32_t smem_u32(const void* p) {
    uint32_t a; asm("{ .reg .u64 t; cvta.to.shared.u64 t, %1; cvt.u32.u64 %0, t; }"
                    : "=r"(a) : "l"(p));
    return a;
}
__device__ __forceinline__ void ldsm_x4(uint32_t* r, uint32_t addr) {
    asm volatile("ldmatrix.sync.aligned.m8n8.x4.shared.b16 {%0,%1,%2,%3}, [%4];"
                 : "=r"(r[0]), "=r"(r[1]), "=r"(r[2]), "=r"(r[3]) : "r"(addr));
}
__device__ __forceinline__ void mma_bf16(float* c, const uint32_t* a,
                                         uint32_t b0, uint32_t b1) {
    asm volatile("mma.sync.aligned.m16n8k16.row.col.f32.bf16.bf16.f32 "
                 "{%0,%1,%2,%3}, {%4,%5,%6,%7}, {%8,%9}, {%0,%1,%2,%3};"
                 : "+f"(c[0]), "+f"(c[1]), "+f"(c[2]), "+f"(c[3])
                 : "r"(a[0]), "r"(a[1]), "r"(a[2]), "r"(a[3]), "r"(b0), "r"(b1));
}

// swizzled byte offset inside a 128-row x 128B tile
__device__ __forceinline__ uint32_t tile_off(int row, int segByte) {
    return (uint32_t)(row * 128 + (segByte ^ ((row & 7) * 16)));
}
// ldmatrix lane address: rows base+L%16, 16B col quad = ks*32 + (L>>4)*16
__device__ __forceinline__ uint32_t frag_addr(uint32_t tbase, int rowbase, int ks, int lane) {
    int r = rowbase + (lane & 15);
    return tbase + tile_off(r, ks * 32 + (lane >> 4) * 16);
}

// ================= bf16-split conversion kernels =================
__global__ __launch_bounds__(256) void split_rows(const float* __restrict__ in,
                                                  bf16* __restrict__ oh,
                                                  bf16* __restrict__ ol, int n4)
{
    int idx = blockIdx.x * blockDim.x + threadIdx.x;
    if (idx >= n4) return;
    float4 v = *(const float4*)(in + idx * 4);
    float f[4] = {v.x, v.y, v.z, v.w};
#pragma unroll
    for (int i = 0; i < 4; i++) {
        bf16 h = __float2bfloat16_rn(f[i]);
        oh[idx * 4 + i] = h;
        ol[idx * 4 + i] = __float2bfloat16_rn(f[i] - __bfloat162float(h));
    }
}

// in [K][N] f32 -> out [N][K] bf16 hi/lo (transpose)
__global__ __launch_bounds__(256) void split_T(const float* __restrict__ in,
                                               bf16* __restrict__ oh,
                                               bf16* __restrict__ ol, int K, int N)
{
    __shared__ float t[32][33];
    int n0 = blockIdx.x * 32, k0 = blockIdx.y * 32;
    int tx = threadIdx.x & 31, ty = threadIdx.x >> 5;   // 32 x 8
#pragma unroll
    for (int r = 0; r < 4; r++)
        t[ty + 8 * r][tx] = in[(size_t)(k0 + ty + 8 * r) * N + n0 + tx];
    __syncthreads();
#pragma unroll
    for (int r = 0; r < 4; r++) {
        float v = t[tx][ty + 8 * r];
        bf16 h = __float2bfloat16_rn(v);
        size_t o = (size_t)(n0 + ty + 8 * r) * K + k0 + tx;
        oh[o] = h;
        ol[o] = __float2bfloat16_rn(v - __bfloat162float(h));
    }
}

// ================= bf16-split GEMM via mma.sync (HMMA) ==========================
// C[M,N] = Ah*Bh + Ah*Bl + Al*Bh; A [M][K] bf16 rows, B [N][K] bf16 rows (B^T).
// CTA = 128x128 tile, BK=64, 8 warps x (32x64) warp tiles.
#define GEMM_SMEM (65536)

__global__ __launch_bounds__(256, 1) void gemm_mma(const bf16* __restrict__ Ah,
                                                   const bf16* __restrict__ Al,
                                                   const bf16* __restrict__ Bh,
                                                   const bf16* __restrict__ Bl,
                                                   float* __restrict__ C,
                                                   int N, int K)
{
    extern __shared__ char dsm[];
    uint32_t sbase = smem_u32(dsm);
    uint32_t tAh = sbase, tAl = sbase + 16384, tBh = sbase + 32768, tBl = sbase + 49152;

    int tid = threadIdx.x;
    int w = tid >> 5, lane = tid & 31;
    int wm = w & 3, wn = w >> 2;       // warp tile: rows wm*32, cols wn*64
    int bx = blockIdx.x, by = blockIdx.y;

    const bf16* Ah_b = Ah + (size_t)(by * 128) * K;
    const bf16* Al_b = Al + (size_t)(by * 128) * K;
    const bf16* Bh_b = Bh + (size_t)(bx * 128) * K;
    const bf16* Bl_b = Bl + (size_t)(bx * 128) * K;

    float acc[2][8][4];
#pragma unroll
    for (int mi = 0; mi < 2; mi++)
#pragma unroll
        for (int ni = 0; ni < 8; ni++)
#pragma unroll
            for (int q = 0; q < 4; q++) acc[mi][ni][q] = 0.f;

    for (int kc = 0; kc < K; kc += 64) {
        // ---- load 4 tiles (128 rows x 64 bf16, SW128-swizzled) ----
#pragma unroll
        for (int l = 0; l < 4; l++) {
            int s = tid + l * 256;
            int m = s >> 3;
            int seg = s & 7;
            uint32_t so = tile_off(m, seg * 16);
            *(uint4*)(dsm + (tAh - sbase) + so) = *(const uint4*)(Ah_b + (size_t)m * K + kc + seg * 8);
            *(uint4*)(dsm + (tAl - sbase) + so) = *(const uint4*)(Al_b + (size_t)m * K + kc + seg * 8);
            *(uint4*)(dsm + (tBh - sbase) + so) = *(const uint4*)(Bh_b + (size_t)m * K + kc + seg * 8);
            *(uint4*)(dsm + (tBl - sbase) + so) = *(const uint4*)(Bl_b + (size_t)m * K + kc + seg * 8);
        }
        __syncthreads();

#pragma unroll
        for (int ks = 0; ks < 4; ks++) {
            uint32_t ah[2][4], al[2][4];
#pragma unroll
            for (int mi = 0; mi < 2; mi++) {
                ldsm_x4(ah[mi], frag_addr(tAh, wm * 32 + mi * 16, ks, lane));
                ldsm_x4(al[mi], frag_addr(tAl, wm * 32 + mi * 16, ks, lane));
            }
            uint32_t bh[4][4], bl[4][4];
#pragma unroll
            for (int n4 = 0; n4 < 4; n4++) {
                ldsm_x4(bh[n4], frag_addr(tBh, wn * 64 + n4 * 16, ks, lane));
                ldsm_x4(bl[n4], frag_addr(tBl, wn * 64 + n4 * 16, ks, lane));
            }
            // mats from x4 over n16: r0=(n0-7,k0-7) r1=(n8-15,k0-7) r2=(n0-7,k8-15) r3=(n8-15,k8-15)
#pragma unroll
            for (int mi = 0; mi < 2; mi++)
#pragma unroll
                for (int n4 = 0; n4 < 4; n4++) {
                    mma_bf16(acc[mi][n4 * 2],     ah[mi], bh[n4][0], bh[n4][2]);
                    mma_bf16(acc[mi][n4 * 2 + 1], ah[mi], bh[n4][1], bh[n4][3]);
                    mma_bf16(acc[mi][n4 * 2],     ah[mi], bl[n4][0], bl[n4][2]);
                    mma_bf16(acc[mi][n4 * 2 + 1], ah[mi], bl[n4][1], bl[n4][3]);
                    mma_bf16(acc[mi][n4 * 2],     al[mi], bh[n4][0], bh[n4][2]);
                    mma_bf16(acc[mi][n4 * 2 + 1], al[mi], bh[n4][1], bh[n4][3]);
                }
        }
        __syncthreads();
    }

    // ---- epilogue: c-frag layout -> gmem f32 ----
    int g = lane >> 2, t4 = lane & 3;
#pragma unroll
    for (int mi = 0; mi < 2; mi++)
#pragma unroll
        for (int ni = 0; ni < 8; ni++) {
            int row = by * 128 + wm * 32 + mi * 16 + g;
            int col = bx * 128 + wn * 64 + ni * 8 + t4 * 2;
            *(float2*)(C + (size_t)row * N + col) = make_float2(acc[mi][ni][0], acc[mi][ni][1]);
            *(float2*)(C + (size_t)(row + 8) * N + col) = make_float2(acc[mi][ni][2], acc[mi][ni][3]);
        }
}

// ================= RoPE + transpose to (bh, s, d); v copy =======================
__global__ __launch_bounds__(256) void rope_transpose(const float* __restrict__ rc,
                                                      const float* __restrict__ rs)
{
    int idx = blockIdx.x * blockDim.x + threadIdx.x;
    if (idx >= BHN * SEQ * HALF) return;
    int t  = idx & (HALF - 1);
    int s  = (idx >> 5) & (SEQ - 1);
    int bh = idx >> 16;
    int b  = bh >> 4;
    int h  = bh & (NH - 1);

    size_t src = ((size_t)(b * SEQ + s)) * (3 * DMODEL) + h * DH + 2 * t;
    float c  = rc[s * DH + 2 * t];
    float sn = rs[s * DH + 2 * t];

    float2 q = *(const float2*)(g_qkv + src);
    float2 k = *(const float2*)(g_qkv + src + DMODEL);
    float2 v = *(const float2*)(g_qkv + src + 2 * DMODEL);

    size_t dst = ((size_t)bh * SEQ + s) * DH + 2 * t;
    *(float2*)(g_q + dst) = make_float2(q.x * c - q.y * sn, q.y * c + q.x * sn);
    *(float2*)(g_k + dst) = make_float2(k.x * c - k.y * sn, k.y * c + k.x * sn);
    *(float2*)(g_v + dst) = v;
}

// ================= fused flash attention (dual-triangle select) =================
union KPu {
    u64   k[64][32];
    float p[64 * 64];
};

__global__ __launch_bounds__(256, 2) void flash_kernel()
{
    __shared__ u64  Qp[64][32];
    __shared__ KPu  KP;
    __shared__ u64  Vt[64][32];

    int tid = threadIdx.x;
    int tx = tid & 15, ty = tid >> 4;
    int it = blockIdx.x;
    int bh = blockIdx.y;
    int i0 = it * 64;
    int b = bh >> 4, h = bh & (NH - 1);

    const float* Qg = g_q + ((size_t)bh * SEQ + i0) * DH;
    const float* Kg = g_k + (size_t)bh * SEQ * DH;
    const float* Vg = g_v + (size_t)bh * SEQ * DH;

#pragma unroll
    for (int l = 0; l < 4; l++) {
        int id = tid + l * 256;
        int i = id >> 4;
        int f4 = id & 15;
        int sw = i & 15;
        float4 v = *(const float4*)(Qg + (size_t)i * DH + f4 * 4);
        Qp[i][(f4 * 2) ^ sw]     = pack2(v.x, v.y);
        Qp[i][(f4 * 2 + 1) ^ sw] = pack2(v.z, v.w);
    }

    u64 o2[4][4];
#pragma unroll
    for (int r = 0; r < 4; r++)
#pragma unroll
        for (int c = 0; c < 4; c++) o2[r][c] = 0ull;
    float m[4], l[4];
#pragma unroll
    for (int r = 0; r < 4; r++) { m[r] = -1e30f; l[r] = 0.f; }

    const float scale = 0.17677669529663687f;

    for (int jt = 0; jt < SEQ / 64; jt++) {
        int j0 = jt * 64;
        __syncthreads();

#pragma unroll
        for (int lld = 0; lld < 4; lld++) {
            int id = tid + lld * 256;
            int j = id >> 4;
            int f4 = id & 15;
            int sw = j & 15;
            float4 kv = *(const float4*)(Kg + (size_t)(j0 + j) * DH + f4 * 4);
            KP.k[j][(f4 * 2) ^ sw]     = pack2(kv.x, kv.y);
            KP.k[j][(f4 * 2 + 1) ^ sw] = pack2(kv.z, kv.w);
        }
#pragma unroll
        for (int lld = 0; lld < 4; lld++) {
            int id = tid + lld * 256;
            int jp = id >> 5;
            int e = (id & 31) * 2;
            float2 a = *(const float2*)(Vg + (size_t)(j0 + 2 * jp) * DH + e);
            float2 c = *(const float2*)(Vg + (size_t)(j0 + 2 * jp + 1) * DH + e);
            Vt[e][jp ^ (e & 15)]           = pack2(a.x, c.x);
            Vt[e + 1][jp ^ ((e + 1) & 15)] = pack2(a.y, c.y);
        }
        __syncthreads();

        float s[4][4];
        if (jt != it) {
            int dbase = (jt < it) ? 16 : 0;
            u64 s2[4][4];
#pragma unroll
            for (int r = 0; r < 4; r++)
#pragma unroll
                for (int c = 0; c < 4; c++) s2[r][c] = 0ull;
#pragma unroll
            for (int dd = 0; dd < 16; dd++) {
                int dp = dbase + dd;
                u64 q2[4], k2[4];
#pragma unroll
                for (int r = 0; r < 4; r++) q2[r] = Qp[ty + 16 * r][dp ^ ty];
#pragma unroll
                for (int c = 0; c < 4; c++) k2[c] = KP.k[tx + 16 * c][dp ^ tx];
#pragma unroll
                for (int r = 0; r < 4; r++)
#pragma unroll
                    for (int c = 0; c < 4; c++) s2[r][c] = ffma2(q2[r], k2[c], s2[r][c]);
            }
#pragma unroll
            for (int r = 0; r < 4; r++)
#pragma unroll
                for (int c = 0; c < 4; c++) {
                    float2 u = unpack2(s2[r][c]);
                    s[r][c] = scale * (u.x + u.y);
                }
        } else {
            u64 up2[4][4], dn2[4][4];
#pragma unroll
            for (int r = 0; r < 4; r++)
#pragma unroll
                for (int c = 0; c < 4; c++) { up2[r][c] = 0ull; dn2[r][c] = 0ull; }
#pragma unroll
            for (int dp = 0; dp < 16; dp++) {
                u64 q2[4], k2[4];
#pragma unroll
                for (int r = 0; r < 4; r++) q2[r] = Qp[ty + 16 * r][dp ^ ty];
#pragma unroll
                for (int c = 0; c < 4; c++) k2[c] = KP.k[tx + 16 * c][dp ^ tx];
#pragma unroll
                for (int r = 0; r < 4; r++)
#pragma unroll
                    for (int c = 0; c < 4; c++) up2[r][c] = ffma2(q2[r], k2[c], up2[r][c]);
            }
#pragma unroll
            for (int dp = 16; dp < 32; dp++) {
                u64 q2[4], k2[4];
#pragma unroll
                for (int r = 0; r < 4; r++) q2[r] = Qp[ty + 16 * r][dp ^ ty];
#pragma unroll
                for (int c = 0; c < 4; c++) k2[c] = KP.k[tx + 16 * c][dp ^ tx];
#pragma unroll
                for (int r = 0; r < 4; r++)
#pragma unroll
                    for (int c = 0; c < 4; c++) dn2[r][c] = ffma2(q2[r], k2[c], dn2[r][c]);
            }
#pragma unroll
            for (int r = 0; r < 4; r++) {
                int i = i0 + ty + 16 * r;
#pragma unroll
                for (int c = 0; c < 4; c++) {
                    int j = j0 + tx + 16 * c;
                    float2 u = unpack2(up2[r][c]);
                    float2 d = unpack2(dn2[r][c]);
                    s[r][c] = scale * ((j <= i) ? (d.x + d.y) : (u.x + u.y));
                }
            }
        }

#pragma unroll
        for (int r = 0; r < 4; r++) {
            float cm = fmaxf(fmaxf(s[r][0], s[r][1]), fmaxf(s[r][2], s[r][3]));
#pragma unroll
            for (int off = 8; off > 0; off >>= 1)
                cm = fmaxf(cm, __shfl_xor_sync(0xffffffffu, cm, off, 16));
            float nm = fmaxf(m[r], cm);
            float al = __expf(m[r] - nm);
            m[r] = nm;
            float rsum = 0.f;
#pragma unroll
            for (int c = 0; c < 4; c++) { s[r][c] = __expf(s[r][c] - nm); rsum += s[r][c]; }
#pragma unroll
            for (int off = 8; off > 0; off >>= 1)
                rsum += __shfl_xor_sync(0xffffffffu, rsum, off, 16);
            l[r] = l[r] * al + rsum;
            u64 al2 = pack2(al, al);
#pragma unroll
            for (int c = 0; c < 4; c++) o2[r][c] = fmul2(o2[r][c], al2);
        }

        __syncthreads();
#pragma unroll
        for (int r = 0; r < 4; r++) {
            int i = ty + 16 * r;
#pragma unroll
            for (int c = 0; c < 4; c++) {
                int j = tx + 16 * c;
                KP.p[i * 64 + ((j >> 1) ^ ty) * 2 + (j & 1)] = s[r][c];
            }
        }
        __syncthreads();

#pragma unroll 8
        for (int jp = 0; jp < 32; jp++) {
            u64 p2[4], v2[4];
#pragma unroll
            for (int r = 0; r < 4; r++)
                p2[r] = *(const u64*)&KP.p[(ty + 16 * r) * 64 + ((jp ^ ty) * 2)];
#pragma unroll
            for (int c = 0; c < 4; c++)
                v2[c] = Vt[tx + 16 * c][jp ^ tx];
#pragma unroll
            for (int r = 0; r < 4; r++)
#pragma unroll
                for (int c = 0; c < 4; c++) o2[r][c] = ffma2(p2[r], v2[c], o2[r][c]);
        }
    }

#pragma unroll
    for (int r = 0; r < 4; r++) {
        float invl = 1.f / l[r];
        int i = i0 + ty + 16 * r;
#pragma unroll
        for (int c = 0; c < 4; c++) {
            float2 t = unpack2(o2[r][c]);
            g_ao[(size_t)(b * SEQ + i) * DMODEL + h * DH + tx + 16 * c] = (t.x + t.y) * invl;
        }
    }
}

// =================================================================================
extern "C" void kernel_launch(void* const* d_in, const int* in_sizes, int n_in,
                              void* d_out, int out_size)
{
    const float* x      = (const float*)d_in[0];
    const float* w_qkv  = (const float*)d_in[1];
    const float* w_proj = (const float*)d_in[2];
    const float* rc     = (const float*)d_in[3];
    const float* rs     = (const float*)d_in[4];
    float* out = (float*)d_out;

    float *qkv_ptr, *ao_ptr;
    cudaGetSymbolAddress((void**)&qkv_ptr, g_qkv);
    cudaGetSymbolAddress((void**)&ao_ptr,  g_ao);
    bf16 *xh, *xl, *aoh, *aol, *wqh, *wql, *wph, *wpl;
    cudaGetSymbolAddress((void**)&xh,  g_xh);
    cudaGetSymbolAddress((void**)&xl,  g_xl);
    cudaGetSymbolAddress((void**)&aoh, g_aoh);
    cudaGetSymbolAddress((void**)&aol, g_aol);
    cudaGetSymbolAddress((void**)&wqh, g_wqh);
    cudaGetSymbolAddress((void**)&wql, g_wql);
    cudaGetSymbolAddress((void**)&wph, g_wph);
    cudaGetSymbolAddress((void**)&wpl, g_wpl);

    cudaFuncSetAttribute(gemm_mma, cudaFuncAttributeMaxDynamicSharedMemorySize, GEMM_SMEM);

    // split inputs / weights
    split_rows<<<(MTOK * DMODEL / 4 + 255) / 256, 256>>>(x, xh, xl, MTOK * DMODEL / 4);
    split_T<<<dim3(3 * DMODEL / 32, DMODEL / 32), 256>>>(w_qkv, wqh, wql, DMODEL, 3 * DMODEL);
    split_T<<<dim3(DMODEL / 32, DMODEL / 32), 256>>>(w_proj, wph, wpl, DMODEL, DMODEL);

    // 1) QKV GEMM (HMMA): [4096,1024] @ [1024,3072]
    gemm_mma<<<dim3(3 * DMODEL / 128, MTOK / 128), 256, GEMM_SMEM>>>(xh, xl, wqh, wql,
                                                                     qkv_ptr, 3 * DMODEL, DMODEL);
    // 2) RoPE + transpose
    rope_transpose<<<(BHN * SEQ * HALF + 255) / 256, 256>>>(rc, rs);
    // 3) fused attention
    flash_kernel<<<dim3(SEQ / 64, BHN), 256>>>();
    // 4) split attn out, proj GEMM (HMMA)
    split_rows<<<(MTOK * DMODEL / 4 + 255) / 256, 256>>>(ao_ptr, aoh, aol, MTOK * DMODEL / 4);
    gemm_mma<<<dim3(DMODEL / 128, MTOK / 128), 256, GEMM_SMEM>>>(aoh, aol, wph, wpl,
                                                                 out, DMODEL, DMODEL);
}

// round 6
// speedup vs baseline: 2.5303x; 1.4508x over previous
#include <cuda_runtime.h>
#include <cuda_bf16.h>
#include <math.h>
#include <cstdint>

#define SEQ   2048
#define BATCH 2
#define DMODEL 1024
#define NH    16
#define DH    64
#define HALF  32
#define BHN   (BATCH*NH)        // 32
#define MTOK  (BATCH*SEQ)       // 4096

typedef unsigned long long u64;
typedef __nv_bfloat16 bf16;

// -------- scratch (device globals; no allocation allowed) --------
__device__ float g_qkv[(size_t)MTOK * 3 * DMODEL];   // 4096 x 3072
__device__ float g_ao[(size_t)MTOK * DMODEL];

__device__ bf16 g_xh[(size_t)MTOK * DMODEL];
__device__ bf16 g_xl[(size_t)MTOK * DMODEL];
__device__ bf16 g_aoh[(size_t)MTOK * DMODEL];
__device__ bf16 g_aol[(size_t)MTOK * DMODEL];
__device__ bf16 g_wqh[(size_t)3 * DMODEL * DMODEL];  // [3072][1024] transposed
__device__ bf16 g_wql[(size_t)3 * DMODEL * DMODEL];
__device__ bf16 g_wph[(size_t)DMODEL * DMODEL];      // [1024][1024] transposed
__device__ bf16 g_wpl[(size_t)DMODEL * DMODEL];

// roped q/k and v, bf16 hi/lo, layout (bh, s, d)
__device__ bf16 g_qh2[(size_t)BHN * SEQ * DH];
__device__ bf16 g_ql2[(size_t)BHN * SEQ * DH];
__device__ bf16 g_kh2[(size_t)BHN * SEQ * DH];
__device__ bf16 g_kl2[(size_t)BHN * SEQ * DH];
__device__ bf16 g_vh2[(size_t)BHN * SEQ * DH];
__device__ bf16 g_vl2[(size_t)BHN * SEQ * DH];

// ---------------- helpers ----------------
__device__ __forceinline__ uint32_t smem_u32(const void* p) {
    uint32_t a; asm("{ .reg .u64 t; cvta.to.shared.u64 t, %1; cvt.u32.u64 %0, t; }"
                    : "=r"(a) : "l"(p));
    return a;
}
__device__ __forceinline__ void ldsm_x4(uint32_t* r, uint32_t addr) {
    asm volatile("ldmatrix.sync.aligned.m8n8.x4.shared.b16 {%0,%1,%2,%3}, [%4];"
                 : "=r"(r[0]), "=r"(r[1]), "=r"(r[2]), "=r"(r[3]) : "r"(addr));
}
__device__ __forceinline__ void mma_bf16(float* c, const uint32_t* a,
                                         uint32_t b0, uint32_t b1) {
    asm volatile("mma.sync.aligned.m16n8k16.row.col.f32.bf16.bf16.f32 "
                 "{%0,%1,%2,%3}, {%4,%5,%6,%7}, {%8,%9}, {%0,%1,%2,%3};"
                 : "+f"(c[0]), "+f"(c[1]), "+f"(c[2]), "+f"(c[3])
                 : "r"(a[0]), "r"(a[1]), "r"(a[2]), "r"(a[3]), "r"(b0), "r"(b1));
}
__device__ __forceinline__ uint32_t f2bf2(float lo, float hi) {
    __nv_bfloat162 t = __float22bfloat162_rn(make_float2(lo, hi));
    return *(uint32_t*)&t;
}
__device__ __forceinline__ float2 bf22f2(uint32_t u) {
    __nv_bfloat162 t = *(__nv_bfloat162*)&u;
    return __bfloat1622float2(t);
}

// swizzled byte offset inside a (rows x 128B) tile
__device__ __forceinline__ uint32_t tile_off(int row, int segByte) {
    return (uint32_t)(row * 128 + (segByte ^ ((row & 7) * 16)));
}
__device__ __forceinline__ uint32_t frag_addr(uint32_t tbase, int rowbase, int ks, int lane) {
    int r = rowbase + (lane & 15);
    return tbase + tile_off(r, ks * 32 + (lane >> 4) * 16);
}

// ================= bf16-split conversion kernels =================
__global__ __launch_bounds__(256) void split_rows(const float* __restrict__ in,
                                                  bf16* __restrict__ oh,
                                                  bf16* __restrict__ ol, int n4)
{
    int idx = blockIdx.x * blockDim.x + threadIdx.x;
    if (idx >= n4) return;
    float4 v = *(const float4*)(in + idx * 4);
    float f[4] = {v.x, v.y, v.z, v.w};
#pragma unroll
    for (int i = 0; i < 4; i++) {
        bf16 h = __float2bfloat16_rn(f[i]);
        oh[idx * 4 + i] = h;
        ol[idx * 4 + i] = __float2bfloat16_rn(f[i] - __bfloat162float(h));
    }
}

// in [K][N] f32 -> out [N][K] bf16 hi/lo (transpose)
__global__ __launch_bounds__(256) void split_T(const float* __restrict__ in,
                                               bf16* __restrict__ oh,
                                               bf16* __restrict__ ol, int K, int N)
{
    __shared__ float t[32][33];
    int n0 = blockIdx.x * 32, k0 = blockIdx.y * 32;
    int tx = threadIdx.x & 31, ty = threadIdx.x >> 5;   // 32 x 8
#pragma unroll
    for (int r = 0; r < 4; r++)
        t[ty + 8 * r][tx] = in[(size_t)(k0 + ty + 8 * r) * N + n0 + tx];
    __syncthreads();
#pragma unroll
    for (int r = 0; r < 4; r++) {
        float v = t[tx][ty + 8 * r];
        bf16 h = __float2bfloat16_rn(v);
        size_t o = (size_t)(n0 + ty + 8 * r) * K + k0 + tx;
        oh[o] = h;
        ol[o] = __float2bfloat16_rn(v - __bfloat162float(h));
    }
}

// ================= bf16-split GEMM via mma.sync (HMMA) ==========================
#define GEMM_SMEM (65536)

__global__ __launch_bounds__(256, 1) void gemm_mma(const bf16* __restrict__ Ah,
                                                   const bf16* __restrict__ Al,
                                                   const bf16* __restrict__ Bh,
                                                   const bf16* __restrict__ Bl,
                                                   float* __restrict__ C,
                                                   int N, int K)
{
    extern __shared__ char dsm[];
    uint32_t sbase = smem_u32(dsm);
    uint32_t tAh = sbase, tAl = sbase + 16384, tBh = sbase + 32768, tBl = sbase + 49152;

    int tid = threadIdx.x;
    int w = tid >> 5, lane = tid & 31;
    int wm = w & 3, wn = w >> 2;
    int bx = blockIdx.x, by = blockIdx.y;

    const bf16* Ah_b = Ah + (size_t)(by * 128) * K;
    const bf16* Al_b = Al + (size_t)(by * 128) * K;
    const bf16* Bh_b = Bh + (size_t)(bx * 128) * K;
    const bf16* Bl_b = Bl + (size_t)(bx * 128) * K;

    float acc[2][8][4];
#pragma unroll
    for (int mi = 0; mi < 2; mi++)
#pragma unroll
        for (int ni = 0; ni < 8; ni++)
#pragma unroll
            for (int q = 0; q < 4; q++) acc[mi][ni][q] = 0.f;

    for (int kc = 0; kc < K; kc += 64) {
#pragma unroll
        for (int l = 0; l < 4; l++) {
            int s = tid + l * 256;
            int m = s >> 3;
            int seg = s & 7;
            uint32_t so = tile_off(m, seg * 16);
            *(uint4*)(dsm + (tAh - sbase) + so) = *(const uint4*)(Ah_b + (size_t)m * K + kc + seg * 8);
            *(uint4*)(dsm + (tAl - sbase) + so) = *(const uint4*)(Al_b + (size_t)m * K + kc + seg * 8);
            *(uint4*)(dsm + (tBh - sbase) + so) = *(const uint4*)(Bh_b + (size_t)m * K + kc + seg * 8);
            *(uint4*)(dsm + (tBl - sbase) + so) = *(const uint4*)(Bl_b + (size_t)m * K + kc + seg * 8);
        }
        __syncthreads();

#pragma unroll
        for (int ks = 0; ks < 4; ks++) {
            uint32_t ah[2][4], al[2][4];
#pragma unroll
            for (int mi = 0; mi < 2; mi++) {
                ldsm_x4(ah[mi], frag_addr(tAh, wm * 32 + mi * 16, ks, lane));
                ldsm_x4(al[mi], frag_addr(tAl, wm * 32 + mi * 16, ks, lane));
            }
            uint32_t bh[4][4], bl[4][4];
#pragma unroll
            for (int n4 = 0; n4 < 4; n4++) {
                ldsm_x4(bh[n4], frag_addr(tBh, wn * 64 + n4 * 16, ks, lane));
                ldsm_x4(bl[n4], frag_addr(tBl, wn * 64 + n4 * 16, ks, lane));
            }
#pragma unroll
            for (int mi = 0; mi < 2; mi++)
#pragma unroll
                for (int n4 = 0; n4 < 4; n4++) {
                    mma_bf16(acc[mi][n4 * 2],     ah[mi], bh[n4][0], bh[n4][2]);
                    mma_bf16(acc[mi][n4 * 2 + 1], ah[mi], bh[n4][1], bh[n4][3]);
                    mma_bf16(acc[mi][n4 * 2],     ah[mi], bl[n4][0], bl[n4][2]);
                    mma_bf16(acc[mi][n4 * 2 + 1], ah[mi], bl[n4][1], bl[n4][3]);
                    mma_bf16(acc[mi][n4 * 2],     al[mi], bh[n4][0], bh[n4][2]);
                    mma_bf16(acc[mi][n4 * 2 + 1], al[mi], bh[n4][1], bh[n4][3]);
                }
        }
        __syncthreads();
    }

    int g = lane >> 2, t4 = lane & 3;
#pragma unroll
    for (int mi = 0; mi < 2; mi++)
#pragma unroll
        for (int ni = 0; ni < 8; ni++) {
            int row = by * 128 + wm * 32 + mi * 16 + g;
            int col = bx * 128 + wn * 64 + ni * 8 + t4 * 2;
            *(float2*)(C + (size_t)row * N + col) = make_float2(acc[mi][ni][0], acc[mi][ni][1]);
            *(float2*)(C + (size_t)(row + 8) * N + col) = make_float2(acc[mi][ni][2], acc[mi][ni][3]);
        }
}

// ================= RoPE + transpose + bf16 hi/lo split ==========================
__global__ __launch_bounds__(256) void rope_split(const float* __restrict__ rc,
                                                  const float* __restrict__ rs)
{
    int idx = blockIdx.x * blockDim.x + threadIdx.x;
    if (idx >= BHN * SEQ * HALF) return;
    int t  = idx & (HALF - 1);
    int s  = (idx >> 5) & (SEQ - 1);
    int bh = idx >> 16;
    int b  = bh >> 4;
    int h  = bh & (NH - 1);

    size_t src = ((size_t)(b * SEQ + s)) * (3 * DMODEL) + h * DH + 2 * t;
    float c  = rc[s * DH + 2 * t];
    float sn = rs[s * DH + 2 * t];

    float2 q = *(const float2*)(g_qkv + src);
    float2 k = *(const float2*)(g_qkv + src + DMODEL);
    float2 v = *(const float2*)(g_qkv + src + 2 * DMODEL);

    float qx = q.x * c - q.y * sn, qy = q.y * c + q.x * sn;
    float kx = k.x * c - k.y * sn, ky = k.y * c + k.x * sn;

    size_t dst = ((size_t)bh * SEQ + s) * DH + 2 * t;
    float qxh = __bfloat162float(__float2bfloat16_rn(qx));
    float qyh = __bfloat162float(__float2bfloat16_rn(qy));
    float kxh = __bfloat162float(__float2bfloat16_rn(kx));
    float kyh = __bfloat162float(__float2bfloat16_rn(ky));
    float vxh = __bfloat162float(__float2bfloat16_rn(v.x));
    float vyh = __bfloat162float(__float2bfloat16_rn(v.y));
    *(uint32_t*)(g_qh2 + dst) = f2bf2(qxh, qyh);
    *(uint32_t*)(g_ql2 + dst) = f2bf2(qx - qxh, qy - qyh);
    *(uint32_t*)(g_kh2 + dst) = f2bf2(kxh, kyh);
    *(uint32_t*)(g_kl2 + dst) = f2bf2(kx - kxh, ky - kyh);
    *(uint32_t*)(g_vh2 + dst) = f2bf2(vxh, vyh);
    *(uint32_t*)(g_vl2 + dst) = f2bf2(v.x - vxh, v.y - vyh);
}

// ================= flash attention on mma.sync ==================================
// CTA: 128 i-rows of one (bh). 8 warps x 16 rows; each warp covers full 64-col
// j-tile, so online softmax is warp-local (quad shuffles). QK^T and PV use
// hi/lo bf16 splits (3 products each). Off-diag j-tiles use only the needed
// 32-dim half; the 2 mixed tiles compute both halves + per-element select.
#define FL_SMEM (65536)

__global__ __launch_bounds__(256, 1) void flash_mma()
{
    extern __shared__ char fsm[];
    uint32_t sb = smem_u32(fsm);
    uint32_t QH = sb, QL = sb + 16384;
    uint32_t KH = sb + 32768, KL = sb + 40960;
    uint32_t VH = sb + 49152, VL = sb + 57344;

    int tid = threadIdx.x;
    int w = tid >> 5, lane = tid & 31;
    int g = lane >> 2, t4 = lane & 3;
    int it = blockIdx.x, bh = blockIdx.y;
    int i0 = it * 128;
    int b = bh >> 4, h = bh & (NH - 1);

    const bf16* Qhg = g_qh2 + ((size_t)bh * SEQ + i0) * DH;
    const bf16* Qlg = g_ql2 + ((size_t)bh * SEQ + i0) * DH;
    const bf16* Khg = g_kh2 + (size_t)bh * SEQ * DH;
    const bf16* Klg = g_kl2 + (size_t)bh * SEQ * DH;
    const bf16* Vhg = g_vh2 + (size_t)bh * SEQ * DH;
    const bf16* Vlg = g_vl2 + (size_t)bh * SEQ * DH;

    // ---- load Q tiles (128 rows x 64 bf16, swizzled) ----
#pragma unroll
    for (int l = 0; l < 4; l++) {
        int s = tid + l * 256;
        int row = s >> 3, seg = s & 7;
        uint32_t so = tile_off(row, seg * 16);
        *(uint4*)(fsm + (QH - sb) + so) = *(const uint4*)(Qhg + (size_t)row * DH + seg * 8);
        *(uint4*)(fsm + (QL - sb) + so) = *(const uint4*)(Qlg + (size_t)row * DH + seg * 8);
    }

    float o[8][4];
#pragma unroll
    for (int n = 0; n < 8; n++)
#pragma unroll
        for (int q = 0; q < 4; q++) o[n][q] = 0.f;
    float mr[2] = {-1e30f, -1e30f}, lr[2] = {0.f, 0.f};

    const float scale = 0.17677669529663687f;

    for (int jt = 0; jt < SEQ / 64; jt++) {
        int j0 = jt * 64;
        __syncthreads();

        // ---- load K tiles (64 rows x 64 bf16) ----
#pragma unroll
        for (int l = 0; l < 2; l++) {
            int s = tid + l * 256;
            int row = s >> 3, seg = s & 7;
            uint32_t so = tile_off(row, seg * 16);
            *(uint4*)(fsm + (KH - sb) + so) = *(const uint4*)(Khg + (size_t)(j0 + row) * DH + seg * 8);
            *(uint4*)(fsm + (KL - sb) + so) = *(const uint4*)(Klg + (size_t)(j0 + row) * DH + seg * 8);
        }
        // ---- load V transposed: Vt[e][j] ----
#pragma unroll
        for (int l = 0; l < 2; l++) {
            int s = tid + l * 256;
            int j = s >> 3, seg = s & 7;
            bf16 th[8], tl[8];
            *(uint4*)th = *(const uint4*)(Vhg + (size_t)(j0 + j) * DH + seg * 8);
            *(uint4*)tl = *(const uint4*)(Vlg + (size_t)(j0 + j) * DH + seg * 8);
#pragma unroll
            for (int q = 0; q < 8; q++) {
                int e = seg * 8 + q;
                uint32_t so = tile_off(e, j * 2);
                *(bf16*)(fsm + (VH - sb) + so) = th[q];
                *(bf16*)(fsm + (VL - sb) + so) = tl[q];
            }
        }
        __syncthreads();

        // ---- S = QK^T (split products, half-select) ----
        float sac[8][4];
#pragma unroll
        for (int n = 0; n < 8; n++)
#pragma unroll
            for (int q = 0; q < 4; q++) sac[n][q] = 0.f;

        int mode = (jt <= 2 * it - 1) ? 1 : ((jt >= 2 * it + 2) ? 0 : 2);

        if (mode < 2) {
            int ksb = mode ? 2 : 0;   // dn half = dims 32..63 (byte cols 64..127)
#pragma unroll
            for (int k2 = 0; k2 < 2; k2++) {
                int ks = ksb + k2;
                uint32_t ah[4], al[4];
                ldsm_x4(ah, frag_addr(QH, w * 16, ks, lane));
                ldsm_x4(al, frag_addr(QL, w * 16, ks, lane));
#pragma unroll
                for (int n4 = 0; n4 < 4; n4++) {
                    uint32_t kh4[4], kl4[4];
                    ldsm_x4(kh4, frag_addr(KH, n4 * 16, ks, lane));
                    ldsm_x4(kl4, frag_addr(KL, n4 * 16, ks, lane));
                    mma_bf16(sac[n4 * 2],     ah, kh4[0], kh4[2]);
                    mma_bf16(sac[n4 * 2 + 1], ah, kh4[1], kh4[3]);
                    mma_bf16(sac[n4 * 2],     ah, kl4[0], kl4[2]);
                    mma_bf16(sac[n4 * 2 + 1], ah, kl4[1], kl4[3]);
                    mma_bf16(sac[n4 * 2],     al, kh4[0], kh4[2]);
                    mma_bf16(sac[n4 * 2 + 1], al, kh4[1], kh4[3]);
                }
            }
        } else {
            float sup[8][4];
#pragma unroll
            for (int n = 0; n < 8; n++)
#pragma unroll
                for (int q = 0; q < 4; q++) sup[n][q] = 0.f;
#pragma unroll
            for (int ks = 0; ks < 4; ks++) {
                float (*tgt)[4] = (ks < 2) ? sup : sac;   // up = dims 0..31
                uint32_t ah[4], al[4];
                ldsm_x4(ah, frag_addr(QH, w * 16, ks, lane));
                ldsm_x4(al, frag_addr(QL, w * 16, ks, lane));
#pragma unroll
                for (int n4 = 0; n4 < 4; n4++) {
                    uint32_t kh4[4], kl4[4];
                    ldsm_x4(kh4, frag_addr(KH, n4 * 16, ks, lane));
                    ldsm_x4(kl4, frag_addr(KL, n4 * 16, ks, lane));
                    mma_bf16(tgt[n4 * 2],     ah, kh4[0], kh4[2]);
                    mma_bf16(tgt[n4 * 2 + 1], ah, kh4[1], kh4[3]);
                    mma_bf16(tgt[n4 * 2],     ah, kl4[0], kl4[2]);
                    mma_bf16(tgt[n4 * 2 + 1], ah, kl4[1], kl4[3]);
                    mma_bf16(tgt[n4 * 2],     al, kh4[0], kh4[2]);
                    mma_bf16(tgt[n4 * 2 + 1], al, kh4[1], kh4[3]);
                }
            }
            // select: dn (sac) where j<=i, else up (sup)
#pragma unroll
            for (int n = 0; n < 8; n++)
#pragma unroll
                for (int q = 0; q < 4; q++) {
                    int i = i0 + w * 16 + g + ((q >= 2) ? 8 : 0);
                    int j = j0 + n * 8 + 2 * t4 + (q & 1);
                    sac[n][q] = (j <= i) ? sac[n][q] : sup[n][q];
                }
        }

        // ---- online softmax (warp-local, quad shuffles) ----
        float mx0 = -1e30f, mx1 = -1e30f;
#pragma unroll
        for (int n = 0; n < 8; n++) {
            sac[n][0] *= scale; sac[n][1] *= scale; sac[n][2] *= scale; sac[n][3] *= scale;
            mx0 = fmaxf(mx0, fmaxf(sac[n][0], sac[n][1]));
            mx1 = fmaxf(mx1, fmaxf(sac[n][2], sac[n][3]));
        }
        mx0 = fmaxf(mx0, __shfl_xor_sync(0xffffffffu, mx0, 1));
        mx0 = fmaxf(mx0, __shfl_xor_sync(0xffffffffu, mx0, 2));
        mx1 = fmaxf(mx1, __shfl_xor_sync(0xffffffffu, mx1, 1));
        mx1 = fmaxf(mx1, __shfl_xor_sync(0xffffffffu, mx1, 2));
        float nm0 = fmaxf(mr[0], mx0), nm1 = fmaxf(mr[1], mx1);
        float al0 = __expf(mr[0] - nm0), al1 = __expf(mr[1] - nm1);
        mr[0] = nm0; mr[1] = nm1;
        float sum0 = 0.f, sum1 = 0.f;
#pragma unroll
        for (int n = 0; n < 8; n++) {
            sac[n][0] = __expf(sac[n][0] - nm0); sum0 += sac[n][0];
            sac[n][1] = __expf(sac[n][1] - nm0); sum0 += sac[n][1];
            sac[n][2] = __expf(sac[n][2] - nm1); sum1 += sac[n][2];
            sac[n][3] = __expf(sac[n][3] - nm1); sum1 += sac[n][3];
            o[n][0] *= al0; o[n][1] *= al0; o[n][2] *= al1; o[n][3] *= al1;
        }
        sum0 += __shfl_xor_sync(0xffffffffu, sum0, 1);
        sum0 += __shfl_xor_sync(0xffffffffu, sum0, 2);
        sum1 += __shfl_xor_sync(0xffffffffu, sum1, 1);
        sum1 += __shfl_xor_sync(0xffffffffu, sum1, 2);
        lr[0] = lr[0] * al0 + sum0;
        lr[1] = lr[1] * al1 + sum1;

        // ---- PV: P (c-frag) -> A-frags hi/lo in registers, B from Vt ----
#pragma unroll
        for (int kt = 0; kt < 4; kt++) {
            uint32_t pha[4], pla[4];
#pragma unroll
            for (int half = 0; half < 2; half++) {
                float s0 = sac[2 * kt + half][0], s1 = sac[2 * kt + half][1];
                float s2 = sac[2 * kt + half][2], s3 = sac[2 * kt + half][3];
                uint32_t h01 = f2bf2(s0, s1), h23 = f2bf2(s2, s3);
                float2 f01 = bf22f2(h01), f23 = bf22f2(h23);
                pha[half * 2 + 0] = h01;           // wait: index mapping below
                pha[half * 2 + 1] = h23;
                pla[half * 2 + 0] = f2bf2(s0 - f01.x, s1 - f01.y);
                pla[half * 2 + 1] = f2bf2(s2 - f23.x, s3 - f23.y);
            }
            // reorder to a-frag: a0=(g,k0-7)=tile2kt rowg, a1=(g+8,k0-7)=tile2kt rowg8,
            // a2=(g,k8-15)=tile2kt+1 rowg, a3=(g+8,k8-15)
            uint32_t pa[4] = {pha[0], pha[1], pha[2], pha[3]};
            uint32_t pl4[4] = {pla[0], pla[1], pla[2], pla[3]};
#pragma unroll
            for (int n4 = 0; n4 < 4; n4++) {
                uint32_t vh4[4], vl4[4];
                ldsm_x4(vh4, frag_addr(VH, n4 * 16, kt, lane));
                ldsm_x4(vl4, frag_addr(VL, n4 * 16, kt, lane));
                mma_bf16(o[n4 * 2],     pa, vh4[0], vh4[2]);
                mma_bf16(o[n4 * 2 + 1], pa, vh4[1], vh4[3]);
                mma_bf16(o[n4 * 2],     pa, vl4[0], vl4[2]);
                mma_bf16(o[n4 * 2 + 1], pa, vl4[1], vl4[3]);
                mma_bf16(o[n4 * 2],     pl4, vh4[0], vh4[2]);
                mma_bf16(o[n4 * 2 + 1], pl4, vh4[1], vh4[3]);
            }
        }
    }

    // ---- epilogue ----
    float inv0 = 1.f / lr[0], inv1 = 1.f / lr[1];
    int i_g0 = i0 + w * 16 + g;
#pragma unroll
    for (int n = 0; n < 8; n++) {
        int col = h * DH + n * 8 + 2 * t4;
        *(float2*)(g_ao + (size_t)(b * SEQ + i_g0) * DMODEL + col) =
            make_float2(o[n][0] * inv0, o[n][1] * inv0);
        *(float2*)(g_ao + (size_t)(b * SEQ + i_g0 + 8) * DMODEL + col) =
            make_float2(o[n][2] * inv1, o[n][3] * inv1);
    }
}

// =================================================================================
extern "C" void kernel_launch(void* const* d_in, const int* in_sizes, int n_in,
                              void* d_out, int out_size)
{
    const float* x      = (const float*)d_in[0];
    const float* w_qkv  = (const float*)d_in[1];
    const float* w_proj = (const float*)d_in[2];
    const float* rc     = (const float*)d_in[3];
    const float* rs     = (const float*)d_in[4];
    float* out = (float*)d_out;

    float *qkv_ptr, *ao_ptr;
    cudaGetSymbolAddress((void**)&qkv_ptr, g_qkv);
    cudaGetSymbolAddress((void**)&ao_ptr,  g_ao);
    bf16 *xh, *xl, *aoh, *aol, *wqh, *wql, *wph, *wpl;
    cudaGetSymbolAddress((void**)&xh,  g_xh);
    cudaGetSymbolAddress((void**)&xl,  g_xl);
    cudaGetSymbolAddress((void**)&aoh, g_aoh);
    cudaGetSymbolAddress((void**)&aol, g_aol);
    cudaGetSymbolAddress((void**)&wqh, g_wqh);
    cudaGetSymbolAddress((void**)&wql, g_wql);
    cudaGetSymbolAddress((void**)&wph, g_wph);
    cudaGetSymbolAddress((void**)&wpl, g_wpl);

    cudaFuncSetAttribute(gemm_mma,  cudaFuncAttributeMaxDynamicSharedMemorySize, GEMM_SMEM);
    cudaFuncSetAttribute(flash_mma, cudaFuncAttributeMaxDynamicSharedMemorySize, FL_SMEM);

    // split inputs / weights
    split_rows<<<(MTOK * DMODEL / 4 + 255) / 256, 256>>>(x, xh, xl, MTOK * DMODEL / 4);
    split_T<<<dim3(3 * DMODEL / 32, DMODEL / 32), 256>>>(w_qkv, wqh, wql, DMODEL, 3 * DMODEL);
    split_T<<<dim3(DMODEL / 32, DMODEL / 32), 256>>>(w_proj, wph, wpl, DMODEL, DMODEL);

    // 1) QKV GEMM (HMMA)
    gemm_mma<<<dim3(3 * DMODEL / 128, MTOK / 128), 256, GEMM_SMEM>>>(xh, xl, wqh, wql,
                                                                     qkv_ptr, 3 * DMODEL, DMODEL);
    // 2) RoPE + transpose + split
    rope_split<<<(BHN * SEQ * HALF + 255) / 256, 256>>>(rc, rs);
    // 3) flash attention (HMMA)
    flash_mma<<<dim3(SEQ / 128, BHN), 256, FL_SMEM>>>();
    // 4) split attn out, proj GEMM (HMMA)
    split_rows<<<(MTOK * DMODEL / 4 + 255) / 256, 256>>>(ao_ptr, aoh, aol, MTOK * DMODEL / 4);
    gemm_mma<<<dim3(DMODEL / 128, MTOK / 128), 256, GEMM_SMEM>>>(aoh, aol, wph, wpl,
                                                                 out, DMODEL, DMODEL);
}

// round 7
// speedup vs baseline: 3.7163x; 1.4688x over previous
#include <cuda_runtime.h>
#include <cuda_bf16.h>
#include <math.h>
#include <cstdint>

#define SEQ   2048
#define BATCH 2
#define DMODEL 1024
#define NH    16
#define DH    64
#define HALF  32
#define BHN   (BATCH*NH)        // 32
#define MTOK  (BATCH*SEQ)       // 4096

typedef unsigned long long u64;
typedef __nv_bfloat16 bf16;

// -------- scratch (device globals; no allocation allowed) --------
__device__ float g_qkv[(size_t)MTOK * 3 * DMODEL];   // 4096 x 3072

__device__ bf16 g_xh[(size_t)MTOK * DMODEL];
__device__ bf16 g_xl[(size_t)MTOK * DMODEL];
__device__ bf16 g_aoh[(size_t)MTOK * DMODEL];
__device__ bf16 g_aol[(size_t)MTOK * DMODEL];
__device__ bf16 g_wqh[(size_t)3 * DMODEL * DMODEL];  // [3072][1024] transposed
__device__ bf16 g_wql[(size_t)3 * DMODEL * DMODEL];
__device__ bf16 g_wph[(size_t)DMODEL * DMODEL];      // [1024][1024] transposed
__device__ bf16 g_wpl[(size_t)DMODEL * DMODEL];

// roped q/k and v, bf16 hi/lo, layout (bh, s, d)
__device__ bf16 g_qh2[(size_t)BHN * SEQ * DH];
__device__ bf16 g_ql2[(size_t)BHN * SEQ * DH];
__device__ bf16 g_kh2[(size_t)BHN * SEQ * DH];
__device__ bf16 g_kl2[(size_t)BHN * SEQ * DH];
__device__ bf16 g_vh2[(size_t)BHN * SEQ * DH];
__device__ bf16 g_vl2[(size_t)BHN * SEQ * DH];

// ---------------- helpers ----------------
__device__ __forceinline__ uint32_t smem_u32(const void* p) {
    uint32_t a; asm("{ .reg .u64 t; cvta.to.shared.u64 t, %1; cvt.u32.u64 %0, t; }"
                    : "=r"(a) : "l"(p));
    return a;
}
__device__ __forceinline__ void ldsm_x4(uint32_t* r, uint32_t addr) {
    asm volatile("ldmatrix.sync.aligned.m8n8.x4.shared.b16 {%0,%1,%2,%3}, [%4];"
                 : "=r"(r[0]), "=r"(r[1]), "=r"(r[2]), "=r"(r[3]) : "r"(addr));
}
__device__ __forceinline__ void ldsm_x4_t(uint32_t* r, uint32_t addr) {
    asm volatile("ldmatrix.sync.aligned.m8n8.x4.trans.shared.b16 {%0,%1,%2,%3}, [%4];"
                 : "=r"(r[0]), "=r"(r[1]), "=r"(r[2]), "=r"(r[3]) : "r"(addr));
}
__device__ __forceinline__ void mma_bf16(float* c, const uint32_t* a,
                                         uint32_t b0, uint32_t b1) {
    asm volatile("mma.sync.aligned.m16n8k16.row.col.f32.bf16.bf16.f32 "
                 "{%0,%1,%2,%3}, {%4,%5,%6,%7}, {%8,%9}, {%0,%1,%2,%3};"
                 : "+f"(c[0]), "+f"(c[1]), "+f"(c[2]), "+f"(c[3])
                 : "r"(a[0]), "r"(a[1]), "r"(a[2]), "r"(a[3]), "r"(b0), "r"(b1));
}
__device__ __forceinline__ void cpa16(uint32_t smem, const void* g) {
    asm volatile("cp.async.cg.shared.global [%0], [%1], 16;" :: "r"(smem), "l"(g));
}
#define CPA_COMMIT() asm volatile("cp.async.commit_group;" ::: "memory")
#define CPA_WAIT(n)  asm volatile("cp.async.wait_group %0;" :: "n"(n) : "memory")

__device__ __forceinline__ uint32_t f2bf2(float lo, float hi) {
    __nv_bfloat162 t = __float22bfloat162_rn(make_float2(lo, hi));
    return *(uint32_t*)&t;
}
__device__ __forceinline__ float2 bf22f2(uint32_t u) {
    __nv_bfloat162 t = *(__nv_bfloat162*)&u;
    return __bfloat1622float2(t);
}

// swizzled byte offset inside a (rows x 128B) tile
__device__ __forceinline__ uint32_t tile_off(int row, int segByte) {
    return (uint32_t)(row * 128 + (segByte ^ ((row & 7) * 16)));
}
__device__ __forceinline__ uint32_t frag_addr(uint32_t tbase, int rowbase, int ks, int lane) {
    int r = rowbase + (lane & 15);
    return tbase + tile_off(r, ks * 32 + (lane >> 4) * 16);
}

// ================= bf16-split conversion kernels =================
__global__ __launch_bounds__(256) void split_rows(const float* __restrict__ in,
                                                  bf16* __restrict__ oh,
                                                  bf16* __restrict__ ol, int n4)
{
    int idx = blockIdx.x * blockDim.x + threadIdx.x;
    if (idx >= n4) return;
    float4 v = *(const float4*)(in + idx * 4);
    float f[4] = {v.x, v.y, v.z, v.w};
#pragma unroll
    for (int i = 0; i < 4; i++) {
        bf16 h = __float2bfloat16_rn(f[i]);
        oh[idx * 4 + i] = h;
        ol[idx * 4 + i] = __float2bfloat16_rn(f[i] - __bfloat162float(h));
    }
}

// in [K][N] f32 -> out [N][K] bf16 hi/lo (transpose)
__global__ __launch_bounds__(256) void split_T(const float* __restrict__ in,
                                               bf16* __restrict__ oh,
                                               bf16* __restrict__ ol, int K, int N)
{
    __shared__ float t[32][33];
    int n0 = blockIdx.x * 32, k0 = blockIdx.y * 32;
    int tx = threadIdx.x & 31, ty = threadIdx.x >> 5;   // 32 x 8
#pragma unroll
    for (int r = 0; r < 4; r++)
        t[ty + 8 * r][tx] = in[(size_t)(k0 + ty + 8 * r) * N + n0 + tx];
    __syncthreads();
#pragma unroll
    for (int r = 0; r < 4; r++) {
        float v = t[tx][ty + 8 * r];
        bf16 h = __float2bfloat16_rn(v);
        size_t o = (size_t)(n0 + ty + 8 * r) * K + k0 + tx;
        oh[o] = h;
        ol[o] = __float2bfloat16_rn(v - __bfloat162float(h));
    }
}

// ================= bf16-split GEMM via mma.sync, cp.async 2-stage ===============
#define GEMM_SMEM (131072)

__global__ __launch_bounds__(256, 1) void gemm_mma(const bf16* __restrict__ Ah,
                                                   const bf16* __restrict__ Al,
                                                   const bf16* __restrict__ Bh,
                                                   const bf16* __restrict__ Bl,
                                                   float* __restrict__ C,
                                                   int N, int K)
{
    extern __shared__ char dsm[];
    uint32_t sbase = smem_u32(dsm);

    int tid = threadIdx.x;
    int w = tid >> 5, lane = tid & 31;
    int wm = w & 3, wn = w >> 2;
    int bx = blockIdx.x, by = blockIdx.y;

    const bf16* Ah_b = Ah + (size_t)(by * 128) * K;
    const bf16* Al_b = Al + (size_t)(by * 128) * K;
    const bf16* Bh_b = Bh + (size_t)(bx * 128) * K;
    const bf16* Bl_b = Bl + (size_t)(bx * 128) * K;

    float acc[2][8][4];
#pragma unroll
    for (int mi = 0; mi < 2; mi++)
#pragma unroll
        for (int ni = 0; ni < 8; ni++)
#pragma unroll
            for (int q = 0; q < 4; q++) acc[mi][ni][q] = 0.f;

    int m_ld = tid >> 3, seg = tid & 7;          // 32 rows x 8 segs per pass
    uint32_t so0 = tile_off(m_ld, seg * 16);

    auto load_chunk = [&](int kc, int st) {
        uint32_t sb_st = sbase + (uint32_t)st * 65536u;
#pragma unroll
        for (int l = 0; l < 4; l++) {
            int m = m_ld + l * 32;
            uint32_t so = so0 + (uint32_t)(l * 32 * 128);
            const bf16* srcA = Ah_b + (size_t)m * K + kc + seg * 8;
            const bf16* srcAl = Al_b + (size_t)m * K + kc + seg * 8;
            const bf16* srcB = Bh_b + (size_t)m * K + kc + seg * 8;
            const bf16* srcBl = Bl_b + (size_t)m * K + kc + seg * 8;
            cpa16(sb_st + so, srcA);
            cpa16(sb_st + 16384 + so, srcAl);
            cpa16(sb_st + 32768 + so, srcB);
            cpa16(sb_st + 49152 + so, srcBl);
        }
        CPA_COMMIT();
    };

    int nchunk = K >> 6;
    load_chunk(0, 0);

    for (int ck = 0; ck < nchunk; ck++) {
        if (ck + 1 < nchunk) { load_chunk((ck + 1) << 6, (ck + 1) & 1); CPA_WAIT(1); }
        else                 { CPA_WAIT(0); }
        __syncthreads();

        uint32_t sb_st = sbase + (uint32_t)(ck & 1) * 65536u;
        uint32_t tAh = sb_st, tAl = sb_st + 16384, tBh = sb_st + 32768, tBl = sb_st + 49152;

#pragma unroll
        for (int ks = 0; ks < 4; ks++) {
            uint32_t ah[2][4], al[2][4];
#pragma unroll
            for (int mi = 0; mi < 2; mi++) {
                ldsm_x4(ah[mi], frag_addr(tAh, wm * 32 + mi * 16, ks, lane));
                ldsm_x4(al[mi], frag_addr(tAl, wm * 32 + mi * 16, ks, lane));
            }
            uint32_t bh[4][4], bl[4][4];
#pragma unroll
            for (int n4 = 0; n4 < 4; n4++) {
                ldsm_x4(bh[n4], frag_addr(tBh, wn * 64 + n4 * 16, ks, lane));
                ldsm_x4(bl[n4], frag_addr(tBl, wn * 64 + n4 * 16, ks, lane));
            }
#pragma unroll
            for (int mi = 0; mi < 2; mi++)
#pragma unroll
                for (int n4 = 0; n4 < 4; n4++) {
                    mma_bf16(acc[mi][n4 * 2],     ah[mi], bh[n4][0], bh[n4][2]);
                    mma_bf16(acc[mi][n4 * 2 + 1], ah[mi], bh[n4][1], bh[n4][3]);
                    mma_bf16(acc[mi][n4 * 2],     ah[mi], bl[n4][0], bl[n4][2]);
                    mma_bf16(acc[mi][n4 * 2 + 1], ah[mi], bl[n4][1], bl[n4][3]);
                    mma_bf16(acc[mi][n4 * 2],     al[mi], bh[n4][0], bh[n4][2]);
                    mma_bf16(acc[mi][n4 * 2 + 1], al[mi], bh[n4][1], bh[n4][3]);
                }
        }
        __syncthreads();
    }

    int g = lane >> 2, t4 = lane & 3;
#pragma unroll
    for (int mi = 0; mi < 2; mi++)
#pragma unroll
        for (int ni = 0; ni < 8; ni++) {
            int row = by * 128 + wm * 32 + mi * 16 + g;
            int col = bx * 128 + wn * 64 + ni * 8 + t4 * 2;
            *(float2*)(C + (size_t)row * N + col) = make_float2(acc[mi][ni][0], acc[mi][ni][1]);
            *(float2*)(C + (size_t)(row + 8) * N + col) = make_float2(acc[mi][ni][2], acc[mi][ni][3]);
        }
}

// ================= RoPE + transpose + bf16 hi/lo split ==========================
__global__ __launch_bounds__(256) void rope_split(const float* __restrict__ rc,
                                                  const float* __restrict__ rs)
{
    int idx = blockIdx.x * blockDim.x + threadIdx.x;
    if (idx >= BHN * SEQ * HALF) return;
    int t  = idx & (HALF - 1);
    int s  = (idx >> 5) & (SEQ - 1);
    int bh = idx >> 16;
    int b  = bh >> 4;
    int h  = bh & (NH - 1);

    size_t src = ((size_t)(b * SEQ + s)) * (3 * DMODEL) + h * DH + 2 * t;
    float c  = rc[s * DH + 2 * t];
    float sn = rs[s * DH + 2 * t];

    float2 q = *(const float2*)(g_qkv + src);
    float2 k = *(const float2*)(g_qkv + src + DMODEL);
    float2 v = *(const float2*)(g_qkv + src + 2 * DMODEL);

    float qx = q.x * c - q.y * sn, qy = q.y * c + q.x * sn;
    float kx = k.x * c - k.y * sn, ky = k.y * c + k.x * sn;

    size_t dst = ((size_t)bh * SEQ + s) * DH + 2 * t;
    float qxh = __bfloat162float(__float2bfloat16_rn(qx));
    float qyh = __bfloat162float(__float2bfloat16_rn(qy));
    float kxh = __bfloat162float(__float2bfloat16_rn(kx));
    float kyh = __bfloat162float(__float2bfloat16_rn(ky));
    float vxh = __bfloat162float(__float2bfloat16_rn(v.x));
    float vyh = __bfloat162float(__float2bfloat16_rn(v.y));
    *(uint32_t*)(g_qh2 + dst) = f2bf2(qxh, qyh);
    *(uint32_t*)(g_ql2 + dst) = f2bf2(qx - qxh, qy - qyh);
    *(uint32_t*)(g_kh2 + dst) = f2bf2(kxh, kyh);
    *(uint32_t*)(g_kl2 + dst) = f2bf2(kx - kxh, ky - kyh);
    *(uint32_t*)(g_vh2 + dst) = f2bf2(vxh, vyh);
    *(uint32_t*)(g_vl2 + dst) = f2bf2(v.x - vxh, v.y - vyh);
}

// ================= flash attention on mma.sync, cp.async 2-stage ================
// smem: QH 0..16K, QL 16K..32K; stage st (32KB each): KH, KL, VH, VL (8KB each).
// V kept natural [j][e]; B-frags via ldmatrix.trans.
#define FL_SMEM (98304)

__global__ __launch_bounds__(256, 1) void flash_mma()
{
    extern __shared__ char fsm[];
    uint32_t sb = smem_u32(fsm);
    uint32_t QH = sb, QL = sb + 16384;

    int tid = threadIdx.x;
    int w = tid >> 5, lane = tid & 31;
    int g = lane >> 2, t4 = lane & 3;
    int it = blockIdx.x, bh = blockIdx.y;
    int i0 = it * 128;
    int b = bh >> 4, h = bh & (NH - 1);

    const bf16* Qhg = g_qh2 + ((size_t)bh * SEQ + i0) * DH;
    const bf16* Qlg = g_ql2 + ((size_t)bh * SEQ + i0) * DH;
    const bf16* Khg = g_kh2 + (size_t)bh * SEQ * DH;
    const bf16* Klg = g_kl2 + (size_t)bh * SEQ * DH;
    const bf16* Vhg = g_vh2 + (size_t)bh * SEQ * DH;
    const bf16* Vlg = g_vl2 + (size_t)bh * SEQ * DH;

    int row_ld = tid >> 3, seg = tid & 7;        // Q: 32 rows per pass
    uint32_t soQ = tile_off(row_ld, seg * 16);
    // K/V: 64 rows x 8 segs = 512 slots = 2 passes of 256
    auto load_kv = [&](int j0, int st) {
        uint32_t base = sb + 32768u + (uint32_t)st * 32768u;
#pragma unroll
        for (int l = 0; l < 2; l++) {
            int r = row_ld + l * 32;
            uint32_t so = tile_off(r, seg * 16);
            cpa16(base + so,         Khg + (size_t)(j0 + r) * DH + seg * 8);
            cpa16(base + 8192 + so,  Klg + (size_t)(j0 + r) * DH + seg * 8);
            cpa16(base + 16384 + so, Vhg + (size_t)(j0 + r) * DH + seg * 8);
            cpa16(base + 24576 + so, Vlg + (size_t)(j0 + r) * DH + seg * 8);
        }
        CPA_COMMIT();
    };

    // Q (128 rows x 128B x2) + first K/V in one group
#pragma unroll
    for (int l = 0; l < 4; l++) {
        int r = row_ld + l * 32;
        uint32_t so = tile_off(r, seg * 16);
        cpa16(QH + so, Qhg + (size_t)r * DH + seg * 8);
        cpa16(QL + so, Qlg + (size_t)r * DH + seg * 8);
    }
    load_kv(0, 0);

    float o[8][4];
#pragma unroll
    for (int n = 0; n < 8; n++)
#pragma unroll
        for (int q = 0; q < 4; q++) o[n][q] = 0.f;
    float mr[2] = {-1e30f, -1e30f}, lr[2] = {0.f, 0.f};

    const float scale = 0.17677669529663687f;

    for (int jt = 0; jt < SEQ / 64; jt++) {
        int j0 = jt * 64;
        if (jt + 1 < SEQ / 64) { load_kv(j0 + 64, (jt + 1) & 1); CPA_WAIT(1); }
        else                   { CPA_WAIT(0); }
        __syncthreads();

        uint32_t KB = sb + 32768u + (uint32_t)(jt & 1) * 32768u;
        uint32_t KH = KB, KL = KB + 8192, VH = KB + 16384, VL = KB + 24576;

        // ---- S = QK^T (split products, half-select) ----
        float sac[8][4];
#pragma unroll
        for (int n = 0; n < 8; n++)
#pragma unroll
            for (int q = 0; q < 4; q++) sac[n][q] = 0.f;

        int mode = (jt <= 2 * it - 1) ? 1 : ((jt >= 2 * it + 2) ? 0 : 2);

        if (mode < 2) {
            int ksb = mode ? 2 : 0;   // dn half = dims 32..63
#pragma unroll
            for (int k2 = 0; k2 < 2; k2++) {
                int ks = ksb + k2;
                uint32_t ah[4], al[4];
                ldsm_x4(ah, frag_addr(QH, w * 16, ks, lane));
                ldsm_x4(al, frag_addr(QL, w * 16, ks, lane));
#pragma unroll
                for (int n4 = 0; n4 < 4; n4++) {
                    uint32_t kh4[4], kl4[4];
                    ldsm_x4(kh4, frag_addr(KH, n4 * 16, ks, lane));
                    ldsm_x4(kl4, frag_addr(KL, n4 * 16, ks, lane));
                    mma_bf16(sac[n4 * 2],     ah, kh4[0], kh4[2]);
                    mma_bf16(sac[n4 * 2 + 1], ah, kh4[1], kh4[3]);
                    mma_bf16(sac[n4 * 2],     ah, kl4[0], kl4[2]);
                    mma_bf16(sac[n4 * 2 + 1], ah, kl4[1], kl4[3]);
                    mma_bf16(sac[n4 * 2],     al, kh4[0], kh4[2]);
                    mma_bf16(sac[n4 * 2 + 1], al, kh4[1], kh4[3]);
                }
            }
        } else {
            float sup[8][4];
#pragma unroll
            for (int n = 0; n < 8; n++)
#pragma unroll
                for (int q = 0; q < 4; q++) sup[n][q] = 0.f;
#pragma unroll
            for (int ks = 0; ks < 4; ks++) {
                float (*tgt)[4] = (ks < 2) ? sup : sac;   // up = dims 0..31
                uint32_t ah[4], al[4];
                ldsm_x4(ah, frag_addr(QH, w * 16, ks, lane));
                ldsm_x4(al, frag_addr(QL, w * 16, ks, lane));
#pragma unroll
                for (int n4 = 0; n4 < 4; n4++) {
                    uint32_t kh4[4], kl4[4];
                    ldsm_x4(kh4, frag_addr(KH, n4 * 16, ks, lane));
                    ldsm_x4(kl4, frag_addr(KL, n4 * 16, ks, lane));
                    mma_bf16(tgt[n4 * 2],     ah, kh4[0], kh4[2]);
                    mma_bf16(tgt[n4 * 2 + 1], ah, kh4[1], kh4[3]);
                    mma_bf16(tgt[n4 * 2],     ah, kl4[0], kl4[2]);
                    mma_bf16(tgt[n4 * 2 + 1], ah, kl4[1], kl4[3]);
                    mma_bf16(tgt[n4 * 2],     al, kh4[0], kh4[2]);
                    mma_bf16(tgt[n4 * 2 + 1], al, kh4[1], kh4[3]);
                }
            }
#pragma unroll
            for (int n = 0; n < 8; n++)
#pragma unroll
                for (int q = 0; q < 4; q++) {
                    int i = i0 + w * 16 + g + ((q >= 2) ? 8 : 0);
                    int j = j0 + n * 8 + 2 * t4 + (q & 1);
                    sac[n][q] = (j <= i) ? sac[n][q] : sup[n][q];
                }
        }

        // ---- online softmax (warp-local, quad shuffles) ----
        float mx0 = -1e30f, mx1 = -1e30f;
#pragma unroll
        for (int n = 0; n < 8; n++) {
            sac[n][0] *= scale; sac[n][1] *= scale; sac[n][2] *= scale; sac[n][3] *= scale;
            mx0 = fmaxf(mx0, fmaxf(sac[n][0], sac[n][1]));
            mx1 = fmaxf(mx1, fmaxf(sac[n][2], sac[n][3]));
        }
        mx0 = fmaxf(mx0, __shfl_xor_sync(0xffffffffu, mx0, 1));
        mx0 = fmaxf(mx0, __shfl_xor_sync(0xffffffffu, mx0, 2));
        mx1 = fmaxf(mx1, __shfl_xor_sync(0xffffffffu, mx1, 1));
        mx1 = fmaxf(mx1, __shfl_xor_sync(0xffffffffu, mx1, 2));
        float nm0 = fmaxf(mr[0], mx0), nm1 = fmaxf(mr[1], mx1);
        float al0 = __expf(mr[0] - nm0), al1 = __expf(mr[1] - nm1);
        mr[0] = nm0; mr[1] = nm1;
        float sum0 = 0.f, sum1 = 0.f;
#pragma unroll
        for (int n = 0; n < 8; n++) {
            sac[n][0] = __expf(sac[n][0] - nm0); sum0 += sac[n][0];
            sac[n][1] = __expf(sac[n][1] - nm0); sum0 += sac[n][1];
            sac[n][2] = __expf(sac[n][2] - nm1); sum1 += sac[n][2];
            sac[n][3] = __expf(sac[n][3] - nm1); sum1 += sac[n][3];
            o[n][0] *= al0; o[n][1] *= al0; o[n][2] *= al1; o[n][3] *= al1;
        }
        sum0 += __shfl_xor_sync(0xffffffffu, sum0, 1);
        sum0 += __shfl_xor_sync(0xffffffffu, sum0, 2);
        sum1 += __shfl_xor_sync(0xffffffffu, sum1, 1);
        sum1 += __shfl_xor_sync(0xffffffffu, sum1, 2);
        lr[0] = lr[0] * al0 + sum0;
        lr[1] = lr[1] * al1 + sum1;

        // ---- PV: P (c-frag) -> A-frags hi/lo; B via ldmatrix.trans of V[j][e] --
#pragma unroll
        for (int kt = 0; kt < 4; kt++) {
            uint32_t pa[4], pl4[4];
#pragma unroll
            for (int half = 0; half < 2; half++) {
                float s0 = sac[2 * kt + half][0], s1 = sac[2 * kt + half][1];
                float s2 = sac[2 * kt + half][2], s3 = sac[2 * kt + half][3];
                uint32_t h01 = f2bf2(s0, s1), h23 = f2bf2(s2, s3);
                float2 f01 = bf22f2(h01), f23 = bf22f2(h23);
                pa[half * 2 + 0] = h01;
                pa[half * 2 + 1] = h23;
                pl4[half * 2 + 0] = f2bf2(s0 - f01.x, s1 - f01.y);
                pl4[half * 2 + 1] = f2bf2(s2 - f23.x, s3 - f23.y);
            }
#pragma unroll
            for (int n4 = 0; n4 < 4; n4++) {
                uint32_t vh4[4], vl4[4];
                // rows = j (kt group), byte cols = n4 e-block; trans -> b-frags
                ldsm_x4_t(vh4, frag_addr(VH, kt * 16, n4, lane));
                ldsm_x4_t(vl4, frag_addr(VL, kt * 16, n4, lane));
                mma_bf16(o[n4 * 2],     pa, vh4[0], vh4[1]);
                mma_bf16(o[n4 * 2 + 1], pa, vh4[2], vh4[3]);
                mma_bf16(o[n4 * 2],     pa, vl4[0], vl4[1]);
                mma_bf16(o[n4 * 2 + 1], pa, vl4[2], vl4[3]);
                mma_bf16(o[n4 * 2],     pl4, vh4[0], vh4[1]);
                mma_bf16(o[n4 * 2 + 1], pl4, vh4[2], vh4[3]);
            }
        }
        __syncthreads();
    }

    // ---- epilogue: normalize + fused bf16 hi/lo split ----
    float inv0 = 1.f / lr[0], inv1 = 1.f / lr[1];
    int i_g0 = i0 + w * 16 + g;
#pragma unroll
    for (int n = 0; n < 8; n++) {
        int col = h * DH + n * 8 + 2 * t4;
        float v0 = o[n][0] * inv0, v1 = o[n][1] * inv0;
        float v2 = o[n][2] * inv1, v3 = o[n][3] * inv1;
        uint32_t h01 = f2bf2(v0, v1), h23 = f2bf2(v2, v3);
        float2 f01 = bf22f2(h01), f23 = bf22f2(h23);
        size_t r0 = (size_t)(b * SEQ + i_g0) * DMODEL + col;
        size_t r1 = (size_t)(b * SEQ + i_g0 + 8) * DMODEL + col;
        *(uint32_t*)(g_aoh + r0) = h01;
        *(uint32_t*)(g_aol + r0) = f2bf2(v0 - f01.x, v1 - f01.y);
        *(uint32_t*)(g_aoh + r1) = h23;
        *(uint32_t*)(g_aol + r1) = f2bf2(v2 - f23.x, v3 - f23.y);
    }
}

// =================================================================================
extern "C" void kernel_launch(void* const* d_in, const int* in_sizes, int n_in,
                              void* d_out, int out_size)
{
    const float* x      = (const float*)d_in[0];
    const float* w_qkv  = (const float*)d_in[1];
    const float* w_proj = (const float*)d_in[2];
    const float* rc     = (const float*)d_in[3];
    const float* rs     = (const float*)d_in[4];
    float* out = (float*)d_out;

    float *qkv_ptr;
    cudaGetSymbolAddress((void**)&qkv_ptr, g_qkv);
    bf16 *xh, *xl, *aoh, *aol, *wqh, *wql, *wph, *wpl;
    cudaGetSymbolAddress((void**)&xh,  g_xh);
    cudaGetSymbolAddress((void**)&xl,  g_xl);
    cudaGetSymbolAddress((void**)&aoh, g_aoh);
    cudaGetSymbolAddress((void**)&aol, g_aol);
    cudaGetSymbolAddress((void**)&wqh, g_wqh);
    cudaGetSymbolAddress((void**)&wql, g_wql);
    cudaGetSymbolAddress((void**)&wph, g_wph);
    cudaGetSymbolAddress((void**)&wpl, g_wpl);

    cudaFuncSetAttribute(gemm_mma,  cudaFuncAttributeMaxDynamicSharedMemorySize, GEMM_SMEM);
    cudaFuncSetAttribute(flash_mma, cudaFuncAttributeMaxDynamicSharedMemorySize, FL_SMEM);

    // split inputs / weights
    split_rows<<<(MTOK * DMODEL / 4 + 255) / 256, 256>>>(x, xh, xl, MTOK * DMODEL / 4);
    split_T<<<dim3(3 * DMODEL / 32, DMODEL / 32), 256>>>(w_qkv, wqh, wql, DMODEL, 3 * DMODEL);
    split_T<<<dim3(DMODEL / 32, DMODEL / 32), 256>>>(w_proj, wph, wpl, DMODEL, DMODEL);

    // 1) QKV GEMM (HMMA, pipelined)
    gemm_mma<<<dim3(3 * DMODEL / 128, MTOK / 128), 256, GEMM_SMEM>>>(xh, xl, wqh, wql,
                                                                     qkv_ptr, 3 * DMODEL, DMODEL);
    // 2) RoPE + transpose + split
    rope_split<<<(BHN * SEQ * HALF + 255) / 256, 256>>>(rc, rs);
    // 3) flash attention (HMMA, pipelined; writes aoh/aol directly)
    flash_mma<<<dim3(SEQ / 128, BHN), 256, FL_SMEM>>>();
    // 4) proj GEMM (HMMA, pipelined)
    gemm_mma<<<dim3(DMODEL / 128, MTOK / 128), 256, GEMM_SMEM>>>(aoh, aol, wph, wpl,
                                                                 out, DMODEL, DMODEL);
}